// round 15
// baseline (speedup 1.0000x reference)
#include <cuda_runtime.h>
#include <math.h>

#define Nn      65536
#define Mm      256
#define CTRLD   1024
#define LSTMIN  3072
#define OUTD    2048
#define EPSF    1e-8f

#define PGRID   592            // 4 blocks/SM * 148 SMs
#define PBLK    256
#define NWARP   8
#define MAXRB   128

// ---------------- scratch ----------------
__device__ float g_mem[(size_t)Nn * Mm];
__device__ float g_simw[Nn], g_simr[Nn];
__device__ float g_gates[3 * CTRLD];
__device__ float g_o[4 * 1036];
__device__ float g_kw[4 * Mm], g_kr[4 * Mm], g_e[4 * Mm], g_a[4 * Mm];
__device__ float g_sc[80];
__device__ float g_S[32];
__device__ float g_reads[4 * Mm];
__device__ unsigned long long g_barcnt;

// ---------------- helpers ----------------
__device__ __forceinline__ float warpSum(float v) {
#pragma unroll
    for (int o = 16; o; o >>= 1) v += __shfl_down_sync(0xffffffffu, v, o);
    return v;
}
__device__ __forceinline__ void warpSum3(float& a, float& b, float& c) {
#pragma unroll
    for (int o = 16; o; o >>= 1) {
        a += __shfl_down_sync(0xffffffffu, a, o);
        b += __shfl_down_sync(0xffffffffu, b, o);
        c += __shfl_down_sync(0xffffffffu, c, o);
    }
}
__device__ __forceinline__ void warpSum2(float& a, float& b) {
#pragma unroll
    for (int o = 16; o; o >>= 1) {
        a += __shfl_down_sync(0xffffffffu, a, o);
        b += __shfl_down_sync(0xffffffffu, b, o);
    }
}
__device__ __forceinline__ float blockSumB(float v) {
    __shared__ float sh[8];
    int lane = threadIdx.x & 31, wid = threadIdx.x >> 5;
    v = warpSum(v);
    if (lane == 0) sh[wid] = v;
    __syncthreads();
    float s = sh[0] + sh[1] + sh[2] + sh[3] + sh[4] + sh[5] + sh[6] + sh[7];
    __syncthreads();
    return s;
}
__device__ __forceinline__ float sigmoidf(float x) { return 1.f / (1.f + expf(-x)); }
__device__ __forceinline__ float softplusf(float x) {
    return x > 0.f ? x + log1pf(expf(-x)) : log1pf(expf(x));
}
__device__ __forceinline__ float dot4(float4 a, float4 b) {
    return a.x * b.x + a.y * b.y + a.z * b.z + a.w * b.w;
}
__device__ __forceinline__ float4 apply4(float4 m, float w, float4 e, float4 a) {
    float4 r;
    r.x = m.x * (1.f - w * e.x) + w * a.x;
    r.y = m.y * (1.f - w * e.y) + w * a.y;
    r.z = m.z * (1.f - w * e.z) + w * a.z;
    r.w = m.w * (1.f - w * e.w) + w * a.w;
    return r;
}
__device__ __forceinline__ int rowStart(int b) {
    return (int)(((long long)b << 16) / PGRID);
}
__device__ __forceinline__ void gridbar(int idx) {
    __syncthreads();
    if (threadIdx.x == 0) {
        __threadfence();
        atomicAdd(&g_barcnt, 1ULL);
        unsigned long long target = (unsigned long long)idx * PGRID;
        while (*(volatile unsigned long long*)&g_barcnt < target) __nanosleep(32);
        __threadfence();
    }
    __syncthreads();
}
__device__ __forceinline__ void cpa16(void* sdst, const void* gsrc) {
    unsigned s = (unsigned)__cvta_generic_to_shared(sdst);
    asm volatile("cp.async.cg.shared.global [%0], [%1], 16;" :: "r"(s), "l"(gsrc));
}
#define CPA_COMMIT() asm volatile("cp.async.commit_group;")
#define CPA_WAIT1()  asm volatile("cp.async.wait_group 1;")
#define CPA_WAIT0()  asm volatile("cp.async.wait_group 0;")

// non-hoistable 128-bit shared load (keeps vectors out of the register file)
__device__ __forceinline__ float4 lds128v(const void* p) {
    float4 v; unsigned a = (unsigned)__cvta_generic_to_shared(p);
    asm volatile("ld.shared.v4.f32 {%0,%1,%2,%3}, [%4];"
                 : "=f"(v.x), "=f"(v.y), "=f"(v.z), "=f"(v.w) : "r"(a));
    return v;
}

// ---------------- init ----------------
__global__ void k_init() {
    int t = threadIdx.x;
    if (t == 0) g_barcnt = 0ULL;
    if (t < 32) g_S[t] = 0.f;
    g_reads[t] = 0.f;              // blockDim = 1024
}

// ---------------- the one persistent kernel ----------------
__global__ void __launch_bounds__(PBLK, 4) k_all(
    const float* __restrict__ x, const float* __restrict__ prev_reads,
    const float* __restrict__ prev_h, const float* __restrict__ prev_c,
    const float* __restrict__ mem_in,
    const float* __restrict__ prev_rw, const float* __restrict__ prev_ww,
    const float* __restrict__ W_ih, const float* __restrict__ W_hh,
    const float* __restrict__ b_lstm,
    const float* __restrict__ W_out, const float* __restrict__ b_out,
    const float* __restrict__ Ww, const float* __restrict__ bw,
    const float* __restrict__ Wr, const float* __restrict__ br,
    float* __restrict__ out) {
    __shared__ float4 s_stage[NWARP][2][64];        // 16KB 2-deep cp.async ring
    __shared__ float  s_buf[1024];
    __shared__ float  s_vec[512];                   // staged kr/kw for U1
    __shared__ float  s_dr[MAXRB], s_ss[MAXRB], s_dw[MAXRB];
    __shared__ float  s_wshr[MAXRB], s_wshw[MAXRB];
    __shared__ float  s_w0[MAXRB], s_w1[MAXRB], s_wb[MAXRB];
    __shared__ float  s_wn2[MAXRB], s_wn3[MAXRB];
    __shared__ float  s_acc[Mm];
    const int b = blockIdx.x, t = threadIdx.x, lane = t & 31, wrp = t >> 5;
    const int rs = rowStart(b), re = rowStart(b + 1);
    const int nb = re - rs;
    const int gw = b * NWARP + wrp;

#define PIPE_ISSUE(SRC, RI, BI) do {                                              \
        if ((RI) < re) {                                                          \
            const float4* _row = (const float4*)((SRC) + (size_t)(RI) * Mm);      \
            cpa16(&s_stage[wrp][BI][lane], _row + lane);                          \
            cpa16(&s_stage[wrp][BI][lane + 32], _row + lane + 32);                \
        }                                                                         \
        CPA_COMMIT();                                                             \
    } while (0)

    // ===== phase 1: LSTM gates (warps 0..3071) + mem0 L2 prefetch (rest) =====
    {
        float4* si4 = (float4*)s_stage;             // 16KB staging inside ring
        for (int j = t; j < 512; j += PBLK) si4[j] = ((const float4*)x)[j];
        si4[512 + t] = ((const float4*)prev_reads)[t];
        si4[768 + t] = ((const float4*)prev_h)[t];
        __syncthreads();
        if (gw < 3072) {
            const float4* wa = (const float4*)(W_ih + (size_t)gw * LSTMIN);
            const float4* wh = (const float4*)(W_hh + (size_t)gw * CTRLD);
            float s = 0.f;
#pragma unroll 8
            for (int j = lane; j < 768; j += 32) s += dot4(wa[j], si4[j]);
#pragma unroll 8
            for (int j = lane; j < 256; j += 32) s += dot4(wh[j], si4[768 + j]);
            s = warpSum(s);
            if (lane == 0) g_gates[gw] = s + b_lstm[gw];
        } else {
            int pw = gw - 3072;
            const int TOT4 = Nn * Mm / 4;
            int start = pw * 2522;
            int end = start + 2522; if (end > TOT4) end = TOT4;
            const float4* p = (const float4*)mem_in;
            float acc = 0.f;
            for (int i = start + lane; i < end; i += 32) { float4 v = __ldcg(p + i); acc += v.x + v.w; }
            if (acc == -1.2345e+37f) g_sc[79] = acc;   // never true; defeats DCE
        }
    }
    gridbar(1);

    // ===== phase 2: ctrl (per-block) + head FC GEMV =====
    {
        for (int j = t; j < CTRLD; j += PBLK) {
            float ig = __ldcg(&g_gates[j]);
            float fg = __ldcg(&g_gates[CTRLD + j]);
            float gg = __ldcg(&g_gates[2 * CTRLD + j]);
            s_buf[j] = sigmoidf(fg) * prev_c[j] + sigmoidf(ig) * tanhf(gg);
        }
        __syncthreads();
        if (gw < 4144) {
            const float4* c4 = (const float4*)s_buf;
            int hd = gw / 1036, k = gw % 1036;
            const float* wrow; float bias;
            if (k < 774) { wrow = Ww + ((size_t)hd * 774 + k) * CTRLD; bias = bw[hd * 774 + k]; }
            else { int kk = k - 774; wrow = Wr + ((size_t)hd * 262 + kk) * CTRLD; bias = br[hd * 262 + kk]; }
            const float4* w4 = (const float4*)wrow;
            float s = 0.f;
#pragma unroll 8
            for (int j = lane; j < 256; j += 32) s += dot4(w4[j], c4[j]);
            s = warpSum(s);
            if (lane == 0) g_o[gw] = s + bias;
        }
    }
    gridbar(2);
    PIPE_ISSUE(mem_in, rs + wrp, 0);                // pass0 prefetch (overlaps derive)

    // ===== phase 3: derive (blocks 0-7) + local head0 key + pass0 sims =====
    {
        if (b < 8) {
            int hh = b >> 1, role = b & 1;
            const float* o = g_o + hh * 1036 + (role ? 774 : 0);
            float kv = tanhf(__ldcg(&o[t]));
            (role ? g_kr : g_kw)[hh * Mm + t] = kv;
            if (!role) {
                g_e[hh * Mm + t] = sigmoidf(__ldcg(&o[262 + t]));
                g_a[hh * Mm + t] = tanhf(__ldcg(&o[518 + t]));
            }
            float ss = blockSumB(kv * kv);
            if (t == 0) {
                float* sc = g_sc + b * 8;
                sc[0] = softplusf(__ldcg(&o[256]));
                sc[1] = sigmoidf(__ldcg(&o[257]));
                float s0 = __ldcg(&o[258]), s1 = __ldcg(&o[259]), s2 = __ldcg(&o[260]);
                float mx = fmaxf(s0, fmaxf(s1, s2));
                float e0 = expf(s0 - mx), e1 = expf(s1 - mx), e2 = expf(s2 - mx);
                float es = e0 + e1 + e2;
                sc[2] = e0 / es; sc[3] = e1 / es; sc[4] = e2 / es;
                sc[5] = 1.f + softplusf(__ldcg(&o[261]));
                sc[6] = sqrtf(ss);
            }
        }
        __syncthreads();
        float kv = tanhf(__ldcg(&g_o[t < 256 ? t : 0]));
        if (t < 256) s_buf[t] = kv;
        float kn = sqrtf(blockSumB(t < 256 ? kv * kv : 0.f));
        float beta0 = softplusf(__ldcg(&g_o[256]));
        __syncthreads();
        float4 k0 = ((const float4*)s_buf)[lane], k1 = ((const float4*)s_buf)[lane + 32];
        int bi = 0;
        for (int r = rs + wrp; r < re; r += NWARP) {
            PIPE_ISSUE(mem_in, r + NWARP, bi ^ 1);
            CPA_WAIT1();
            float4 m0 = s_stage[wrp][bi][lane], m1 = s_stage[wrp][bi][lane + 32];
            float dot = dot4(m0, k0) + dot4(m1, k1);
            float ss2 = dot4(m0, m0) + dot4(m1, m1);
            warpSum2(dot, ss2);
            if (lane == 0) { s_dr[r - rs] = dot; s_ss[r - rs] = ss2; }
            bi ^= 1;
        }
        CPA_WAIT0();
        __syncthreads();
        float ess = 0.f;
        if (t < nb) {
            float sim = __fdividef(s_dr[t], sqrtf(s_ss[t]) * kn + EPSF);
            g_simw[rs + t] = sim;
            ess = __expf(beta0 * sim);
        }
        float s = blockSumB(ess);
        if (t == 0) atomicAdd(&g_S[0], s);
    }
    gridbar(3);

#define ADDR_PHASE(HR, HW)                                                          \
    {                                                                               \
        float sumr = 0.f, sumw = 0.f;                                               \
        if (t < nb) {                                                               \
            int i = rs + t;                                                         \
            int ip = (i + 1) & (Nn - 1), im = (i - 1) & (Nn - 1);                   \
            if ((HR) >= 0) {                                                        \
                const float* sc = g_sc + ((HR) * 2 + 1) * 8;                        \
                float beta = __ldcg(&sc[0]), gg = __ldcg(&sc[1]);                   \
                float c0 = __ldcg(&sc[2]), c1 = __ldcg(&sc[3]), c2 = __ldcg(&sc[4]);\
                float gamma = __ldcg(&sc[5]);                                       \
                float gS = __fdividef(gg, __ldcg(&g_S[(HR) * 4 + 2]));              \
                float om = 1.f - gg;                                                \
                const float* pw = prev_rw + (size_t)(HR) * Nn;                      \
                float wgp = gS * __expf(beta * __ldcg(&g_simr[ip])) + om * pw[ip];  \
                float wgc = gS * __expf(beta * __ldcg(&g_simr[i]))  + om * pw[i];   \
                float wgm = gS * __expf(beta * __ldcg(&g_simr[im])) + om * pw[im];  \
                float ws = c0 * wgp + c1 * wgc + c2 * wgm;                          \
                float wsh = __powf(fmaxf(ws, 1e-12f), gamma);                       \
                s_wshr[t] = wsh; sumr = wsh;                                        \
            }                                                                       \
            if ((HW) >= 0) {                                                        \
                const float* sc = g_sc + ((HW) * 2) * 8;                            \
                float beta = __ldcg(&sc[0]), gg = __ldcg(&sc[1]);                   \
                float c0 = __ldcg(&sc[2]), c1 = __ldcg(&sc[3]), c2 = __ldcg(&sc[4]);\
                float gamma = __ldcg(&sc[5]);                                       \
                float gS = __fdividef(gg, __ldcg(&g_S[(HW) * 4 + 0]));              \
                float om = 1.f - gg;                                                \
                const float* pw = prev_ww + (size_t)(HW) * Nn;                      \
                float wgp = gS * __expf(beta * __ldcg(&g_simw[ip])) + om * pw[ip];  \
                float wgc = gS * __expf(beta * __ldcg(&g_simw[i]))  + om * pw[i];   \
                float wgm = gS * __expf(beta * __ldcg(&g_simw[im])) + om * pw[im];  \
                float ws = c0 * wgp + c1 * wgc + c2 * wgm;                          \
                float wsh = __powf(fmaxf(ws, 1e-12f), gamma);                       \
                s_wshw[t] = wsh; sumw = wsh;                                        \
            }                                                                       \
        }                                                                           \
        float sr = blockSumB(sumr);                                                 \
        float sw = blockSumB(sumw);                                                 \
        if (t == 0) {                                                               \
            if ((HR) >= 0) atomicAdd(&g_S[(HR) * 4 + 3], sr);                       \
            if ((HW) >= 0) atomicAdd(&g_S[(HW) * 4 + 1], sw);                       \
        }                                                                           \
    }

    ADDR_PHASE(-1, 0);
    PIPE_ISSUE(mem_in, rs + wrp, 0);                // U0 prefetch (overlaps barrier)
    gridbar(4);

    // ===== U0: read mem0; NO write; sims kr0 / kw1 on n0 = apply(m0, w0) =====
    {
        if (t < nb) s_w0[t] = s_wshw[t] / (__ldcg(&g_S[1]) + EPSF);
        __syncthreads();
        float4 e0 = __ldcg((const float4*)g_e + lane),        e1 = __ldcg((const float4*)g_e + lane + 32);
        float4 a0 = __ldcg((const float4*)g_a + lane),        a1 = __ldcg((const float4*)g_a + lane + 32);
        float4 kr0 = __ldcg((const float4*)g_kr + lane),      kr1 = __ldcg((const float4*)g_kr + lane + 32);
        float4 kw0 = __ldcg((const float4*)(g_kw + Mm) + lane), kw1 = __ldcg((const float4*)(g_kw + Mm) + lane + 32);
        int bi = 0;
        for (int r = rs + wrp; r < re; r += NWARP) {
            PIPE_ISSUE(mem_in, r + NWARP, bi ^ 1);
            CPA_WAIT1();
            float4 m0 = s_stage[wrp][bi][lane], m1 = s_stage[wrp][bi][lane + 32];
            float w = s_w0[r - rs];
            float4 n0 = apply4(m0, w, e0, a0), n1 = apply4(m1, w, e1, a1);
            float dr = dot4(n0, kr0) + dot4(n1, kr1);
            float ss = dot4(n0, n0) + dot4(n1, n1);
            float dw = dot4(n0, kw0) + dot4(n1, kw1);
            warpSum3(dr, ss, dw);
            if (lane == 0) { s_dr[r - rs] = dr; s_ss[r - rs] = ss; s_dw[r - rs] = dw; }
            bi ^= 1;
        }
        CPA_WAIT0();
        __syncthreads();
        float er = 0.f, ew = 0.f;
        if (t < nb) {
            float nrm = sqrtf(s_ss[t]);
            float beta_r = __ldcg(&g_sc[1 * 8 + 0]), kn_r = __ldcg(&g_sc[1 * 8 + 6]);
            float beta_w = __ldcg(&g_sc[2 * 8 + 0]), kn_w = __ldcg(&g_sc[2 * 8 + 6]);
            float simr = __fdividef(s_dr[t], nrm * kn_r + EPSF); g_simr[rs + t] = simr; er = __expf(beta_r * simr);
            float simw = __fdividef(s_dw[t], nrm * kn_w + EPSF); g_simw[rs + t] = simw; ew = __expf(beta_w * simw);
        }
        float sr = blockSumB(er), sw = blockSumB(ew);
        if (t == 0) { atomicAdd(&g_S[2], sr); atomicAdd(&g_S[4], sw); }
    }
    gridbar(5);
    ADDR_PHASE(0, 1);
    PIPE_ISSUE(mem_in, rs + wrp, 0);                // U1 prefetch
    gridbar(6);

    // ===== U1: read mem0; recompute m1 = apply(m0,w0); reads[0] on m1;
    //           write mem2 = apply(m1,w1); sims kr1 / kw2 on mem2 =====
    {
        if (t < nb) {
            s_w1[t] = s_wshw[t] / (__ldcg(&g_S[5]) + EPSF);
            s_wb[t] = s_wshr[t] / (__ldcg(&g_S[3]) + EPSF);
        }
        s_acc[t] = 0.f;
        if (t < 256) { s_vec[t] = __ldcg(&g_kr[Mm + t]); s_vec[256 + t] = __ldcg(&g_kw[2 * Mm + t]); }
        __syncthreads();
        float4 e00 = __ldcg((const float4*)g_e + lane),        e01 = __ldcg((const float4*)g_e + lane + 32);
        float4 a00 = __ldcg((const float4*)g_a + lane),        a01 = __ldcg((const float4*)g_a + lane + 32);
        float4 e10 = __ldcg((const float4*)(g_e + Mm) + lane),  e11 = __ldcg((const float4*)(g_e + Mm) + lane + 32);
        float4 a10 = __ldcg((const float4*)(g_a + Mm) + lane),  a11 = __ldcg((const float4*)(g_a + Mm) + lane + 32);
        const float4* v4 = (const float4*)s_vec;
        float4 racc0 = make_float4(0, 0, 0, 0), racc1 = make_float4(0, 0, 0, 0);
        int bi = 0;
        for (int r = rs + wrp; r < re; r += NWARP) {
            PIPE_ISSUE(mem_in, r + NWARP, bi ^ 1);
            CPA_WAIT1();
            float4 m0 = s_stage[wrp][bi][lane], m1 = s_stage[wrp][bi][lane + 32];
            float w0 = s_w0[r - rs], w1 = s_w1[r - rs], wp = s_wb[r - rs];
            float4 p0 = apply4(m0, w0, e00, a00), p1 = apply4(m1, w0, e01, a01);   // mem1 row
            racc0.x += wp * p0.x; racc0.y += wp * p0.y; racc0.z += wp * p0.z; racc0.w += wp * p0.w;
            racc1.x += wp * p1.x; racc1.y += wp * p1.y; racc1.z += wp * p1.z; racc1.w += wp * p1.w;
            float4 n0 = apply4(p0, w1, e10, a10), n1 = apply4(p1, w1, e11, a11);   // mem2 row
            float4* dst = (float4*)(g_mem + (size_t)r * Mm);
            dst[lane] = n0; dst[lane + 32] = n1;
            float4 krA = lds128v(v4 + lane), krB = lds128v(v4 + lane + 32);
            float4 kwA = lds128v(v4 + 64 + lane), kwB = lds128v(v4 + 64 + lane + 32);
            float dr = dot4(n0, krA) + dot4(n1, krB);
            float ss = dot4(n0, n0) + dot4(n1, n1);
            float dw = dot4(n0, kwA) + dot4(n1, kwB);
            warpSum3(dr, ss, dw);
            if (lane == 0) { s_dr[r - rs] = dr; s_ss[r - rs] = ss; s_dw[r - rs] = dw; }
            bi ^= 1;
        }
        CPA_WAIT0();
        atomicAdd(&s_acc[4 * lane + 0], racc0.x); atomicAdd(&s_acc[4 * lane + 1], racc0.y);
        atomicAdd(&s_acc[4 * lane + 2], racc0.z); atomicAdd(&s_acc[4 * lane + 3], racc0.w);
        atomicAdd(&s_acc[128 + 4 * lane + 0], racc1.x); atomicAdd(&s_acc[128 + 4 * lane + 1], racc1.y);
        atomicAdd(&s_acc[128 + 4 * lane + 2], racc1.z); atomicAdd(&s_acc[128 + 4 * lane + 3], racc1.w);
        __syncthreads();
        float er = 0.f, ew = 0.f;
        if (t < nb) {
            float nrm = sqrtf(s_ss[t]);
            float beta_r = __ldcg(&g_sc[3 * 8 + 0]), kn_r = __ldcg(&g_sc[3 * 8 + 6]);
            float beta_w = __ldcg(&g_sc[4 * 8 + 0]), kn_w = __ldcg(&g_sc[4 * 8 + 6]);
            float simr = __fdividef(s_dr[t], nrm * kn_r + EPSF); g_simr[rs + t] = simr; er = __expf(beta_r * simr);
            float simw = __fdividef(s_dw[t], nrm * kn_w + EPSF); g_simw[rs + t] = simw; ew = __expf(beta_w * simw);
        }
        float sr = blockSumB(er), sw = blockSumB(ew);
        if (t == 0) { atomicAdd(&g_S[6], sr); atomicAdd(&g_S[8], sw); }
        atomicAdd(&g_reads[0 * Mm + t], s_acc[t]);
    }
    gridbar(7);
    ADDR_PHASE(1, 2);
    PIPE_ISSUE(g_mem, rs + wrp, 0);                 // U2 prefetch (own rows)
    gridbar(8);

    // ===== U2: read mem2; reads[1]; sims kr2 / kw3 on mem3; w2 persisted =====
    {
        if (t < nb) {
            s_wn2[t] = s_wshw[t] / (__ldcg(&g_S[9]) + EPSF);
            s_wb[t]  = s_wshr[t] / (__ldcg(&g_S[7]) + EPSF);
        }
        s_acc[t] = 0.f;
        __syncthreads();
        float4 e0 = __ldcg((const float4*)(g_e + 2 * Mm) + lane),  e1 = __ldcg((const float4*)(g_e + 2 * Mm) + lane + 32);
        float4 a0 = __ldcg((const float4*)(g_a + 2 * Mm) + lane),  a1 = __ldcg((const float4*)(g_a + 2 * Mm) + lane + 32);
        float4 kr0 = __ldcg((const float4*)(g_kr + 2 * Mm) + lane), kr1 = __ldcg((const float4*)(g_kr + 2 * Mm) + lane + 32);
        float4 kw0 = __ldcg((const float4*)(g_kw + 3 * Mm) + lane), kw1 = __ldcg((const float4*)(g_kw + 3 * Mm) + lane + 32);
        float4 racc0 = make_float4(0, 0, 0, 0), racc1 = make_float4(0, 0, 0, 0);
        int bi = 0;
        for (int r = rs + wrp; r < re; r += NWARP) {
            PIPE_ISSUE(g_mem, r + NWARP, bi ^ 1);
            CPA_WAIT1();
            float4 m0 = s_stage[wrp][bi][lane], m1 = s_stage[wrp][bi][lane + 32];
            float w = s_wn2[r - rs], wp = s_wb[r - rs];
            racc0.x += wp * m0.x; racc0.y += wp * m0.y; racc0.z += wp * m0.z; racc0.w += wp * m0.w;
            racc1.x += wp * m1.x; racc1.y += wp * m1.y; racc1.z += wp * m1.z; racc1.w += wp * m1.w;
            float4 n0 = apply4(m0, w, e0, a0), n1 = apply4(m1, w, e1, a1);
            float dr = dot4(n0, kr0) + dot4(n1, kr1);
            float ss = dot4(n0, n0) + dot4(n1, n1);
            float dw = dot4(n0, kw0) + dot4(n1, kw1);
            warpSum3(dr, ss, dw);
            if (lane == 0) { s_dr[r - rs] = dr; s_ss[r - rs] = ss; s_dw[r - rs] = dw; }
            bi ^= 1;
        }
        CPA_WAIT0();
        atomicAdd(&s_acc[4 * lane + 0], racc0.x); atomicAdd(&s_acc[4 * lane + 1], racc0.y);
        atomicAdd(&s_acc[4 * lane + 2], racc0.z); atomicAdd(&s_acc[4 * lane + 3], racc0.w);
        atomicAdd(&s_acc[128 + 4 * lane + 0], racc1.x); atomicAdd(&s_acc[128 + 4 * lane + 1], racc1.y);
        atomicAdd(&s_acc[128 + 4 * lane + 2], racc1.z); atomicAdd(&s_acc[128 + 4 * lane + 3], racc1.w);
        __syncthreads();
        float er = 0.f, ew = 0.f;
        if (t < nb) {
            float nrm = sqrtf(s_ss[t]);
            float beta_r = __ldcg(&g_sc[5 * 8 + 0]), kn_r = __ldcg(&g_sc[5 * 8 + 6]);
            float beta_w = __ldcg(&g_sc[6 * 8 + 0]), kn_w = __ldcg(&g_sc[6 * 8 + 6]);
            float simr = __fdividef(s_dr[t], nrm * kn_r + EPSF); g_simr[rs + t] = simr; er = __expf(beta_r * simr);
            float simw = __fdividef(s_dw[t], nrm * kn_w + EPSF); g_simw[rs + t] = simw; ew = __expf(beta_w * simw);
        }
        float sr = blockSumB(er), sw = blockSumB(ew);
        if (t == 0) { atomicAdd(&g_S[10], sr); atomicAdd(&g_S[12], sw); }
        atomicAdd(&g_reads[1 * Mm + t], s_acc[t]);
    }
    gridbar(9);
    ADDR_PHASE(2, 3);
    PIPE_ISSUE(g_mem, rs + wrp, 0);                 // U3 prefetch
    gridbar(10);

    // ===== U3: read mem2; apply w2 then w3; reads[2] on mem3; sim kr3 on mem4 =====
    {
        if (t < nb) {
            s_wn3[t] = s_wshw[t] / (__ldcg(&g_S[13]) + EPSF);
            s_wb[t]  = s_wshr[t] / (__ldcg(&g_S[11]) + EPSF);
        }
        s_acc[t] = 0.f;
        __syncthreads();
        float4 e20 = __ldcg((const float4*)(g_e + 2 * Mm) + lane), e21 = __ldcg((const float4*)(g_e + 2 * Mm) + lane + 32);
        float4 a20 = __ldcg((const float4*)(g_a + 2 * Mm) + lane), a21 = __ldcg((const float4*)(g_a + 2 * Mm) + lane + 32);
        float4 e30 = __ldcg((const float4*)(g_e + 3 * Mm) + lane), e31 = __ldcg((const float4*)(g_e + 3 * Mm) + lane + 32);
        float4 a30 = __ldcg((const float4*)(g_a + 3 * Mm) + lane), a31 = __ldcg((const float4*)(g_a + 3 * Mm) + lane + 32);
        float4 kr0 = __ldcg((const float4*)(g_kr + 3 * Mm) + lane), kr1 = __ldcg((const float4*)(g_kr + 3 * Mm) + lane + 32);
        float4 racc0 = make_float4(0, 0, 0, 0), racc1 = make_float4(0, 0, 0, 0);
        int bi = 0;
        for (int r = rs + wrp; r < re; r += NWARP) {
            PIPE_ISSUE(g_mem, r + NWARP, bi ^ 1);
            CPA_WAIT1();
            float4 m0 = s_stage[wrp][bi][lane], m1 = s_stage[wrp][bi][lane + 32];
            float w2 = s_wn2[r - rs], w3 = s_wn3[r - rs], wp = s_wb[r - rs];
            m0 = apply4(m0, w2, e20, a20); m1 = apply4(m1, w2, e21, a21);   // mem3
            racc0.x += wp * m0.x; racc0.y += wp * m0.y; racc0.z += wp * m0.z; racc0.w += wp * m0.w;
            racc1.x += wp * m1.x; racc1.y += wp * m1.y; racc1.z += wp * m1.z; racc1.w += wp * m1.w;
            float4 n0 = apply4(m0, w3, e30, a30), n1 = apply4(m1, w3, e31, a31);  // mem4
            float dr = dot4(n0, kr0) + dot4(n1, kr1);
            float ss = dot4(n0, n0) + dot4(n1, n1);
            warpSum2(dr, ss);
            if (lane == 0) { s_dr[r - rs] = dr; s_ss[r - rs] = ss; }
            bi ^= 1;
        }
        CPA_WAIT0();
        atomicAdd(&s_acc[4 * lane + 0], racc0.x); atomicAdd(&s_acc[4 * lane + 1], racc0.y);
        atomicAdd(&s_acc[4 * lane + 2], racc0.z); atomicAdd(&s_acc[4 * lane + 3], racc0.w);
        atomicAdd(&s_acc[128 + 4 * lane + 0], racc1.x); atomicAdd(&s_acc[128 + 4 * lane + 1], racc1.y);
        atomicAdd(&s_acc[128 + 4 * lane + 2], racc1.z); atomicAdd(&s_acc[128 + 4 * lane + 3], racc1.w);
        __syncthreads();
        float er = 0.f;
        if (t < nb) {
            float beta_r = __ldcg(&g_sc[7 * 8 + 0]), kn_r = __ldcg(&g_sc[7 * 8 + 6]);
            float simr = __fdividef(s_dr[t], sqrtf(s_ss[t]) * kn_r + EPSF);
            g_simr[rs + t] = simr; er = __expf(beta_r * simr);
        }
        float sr = blockSumB(er);
        if (t == 0) atomicAdd(&g_S[14], sr);
        atomicAdd(&g_reads[2 * Mm + t], s_acc[t]);
    }
    gridbar(11);
    ADDR_PHASE(3, -1);
    PIPE_ISSUE(g_mem, rs + wrp, 0);                 // FINAL prefetch
    // NOTE: no grid barrier here — FINAL uses only block-local s_wshr/s_wn2/s_wn3;
    // the global S15 normalization is deferred to the OUT stage.

    // ===== FINAL: unnormalized reads[3] = sum_r wshr3[r] * mem4[r] =====
    {
        s_acc[t] = 0.f;
        __syncthreads();
        float4 e20 = __ldcg((const float4*)(g_e + 2 * Mm) + lane), e21 = __ldcg((const float4*)(g_e + 2 * Mm) + lane + 32);
        float4 a20 = __ldcg((const float4*)(g_a + 2 * Mm) + lane), a21 = __ldcg((const float4*)(g_a + 2 * Mm) + lane + 32);
        float4 e30 = __ldcg((const float4*)(g_e + 3 * Mm) + lane), e31 = __ldcg((const float4*)(g_e + 3 * Mm) + lane + 32);
        float4 a30 = __ldcg((const float4*)(g_a + 3 * Mm) + lane), a31 = __ldcg((const float4*)(g_a + 3 * Mm) + lane + 32);
        float4 racc0 = make_float4(0, 0, 0, 0), racc1 = make_float4(0, 0, 0, 0);
        int bi = 0;
        for (int r = rs + wrp; r < re; r += NWARP) {
            PIPE_ISSUE(g_mem, r + NWARP, bi ^ 1);
            CPA_WAIT1();
            float4 m0 = s_stage[wrp][bi][lane], m1 = s_stage[wrp][bi][lane + 32];
            float w2 = s_wn2[r - rs], w3 = s_wn3[r - rs], wr = s_wshr[r - rs];
            m0 = apply4(m0, w2, e20, a20); m1 = apply4(m1, w2, e21, a21);
            m0 = apply4(m0, w3, e30, a30); m1 = apply4(m1, w3, e31, a31);
            racc0.x += wr * m0.x; racc0.y += wr * m0.y; racc0.z += wr * m0.z; racc0.w += wr * m0.w;
            racc1.x += wr * m1.x; racc1.y += wr * m1.y; racc1.z += wr * m1.z; racc1.w += wr * m1.w;
            bi ^= 1;
        }
        CPA_WAIT0();
        atomicAdd(&s_acc[4 * lane + 0], racc0.x); atomicAdd(&s_acc[4 * lane + 1], racc0.y);
        atomicAdd(&s_acc[4 * lane + 2], racc0.z); atomicAdd(&s_acc[4 * lane + 3], racc0.w);
        atomicAdd(&s_acc[128 + 4 * lane + 0], racc1.x); atomicAdd(&s_acc[128 + 4 * lane + 1], racc1.y);
        atomicAdd(&s_acc[128 + 4 * lane + 2], racc1.z); atomicAdd(&s_acc[128 + 4 * lane + 3], racc1.w);
        __syncthreads();
        atomicAdd(&g_reads[3 * Mm + t], s_acc[t]);
    }
    gridbar(12);

    // ===== OUT: warp-per-row (blocks 0..255); reads[3] normalized here =====
    if (b < 256) {
        float invS15 = 1.f / (__ldcg(&g_S[15]) + EPSF);
        for (int j = t; j < CTRLD; j += PBLK) {
            float v = __ldcg(&g_reads[j]);
            s_buf[j] = (j < 768) ? v : v * invS15;
        }
        __syncthreads();
        int row = b * 8 + wrp;
        const float4* w4 = (const float4*)(W_out + (size_t)row * CTRLD);
        const float4* r4 = (const float4*)s_buf;
        float s = 0.f;
#pragma unroll 8
        for (int j = lane; j < 256; j += 32) s += dot4(w4[j], r4[j]);
        s = warpSum(s);
        if (lane == 0) out[row] = s + b_out[row];
    }
}

// ---------------- launch ----------------
extern "C" void kernel_launch(void* const* d_in, const int* in_sizes, int n_in,
                              void* d_out, int out_size) {
    const float* x          = (const float*)d_in[0];
    const float* prev_reads = (const float*)d_in[1];
    const float* prev_h     = (const float*)d_in[2];
    const float* prev_c     = (const float*)d_in[3];
    const float* memory     = (const float*)d_in[4];
    const float* prev_rw    = (const float*)d_in[5];
    const float* prev_ww    = (const float*)d_in[6];
    const float* W_ih       = (const float*)d_in[7];
    const float* W_hh       = (const float*)d_in[8];
    const float* b_lstm     = (const float*)d_in[9];
    const float* W_out      = (const float*)d_in[10];
    const float* b_out      = (const float*)d_in[11];
    const float* Ww         = (const float*)d_in[12];
    const float* bw         = (const float*)d_in[13];
    const float* Wr         = (const float*)d_in[14];
    const float* br         = (const float*)d_in[15];
    float* out = (float*)d_out;

    k_init<<<1, 1024>>>();
    k_all<<<PGRID, PBLK>>>(x, prev_reads, prev_h, prev_c, memory, prev_rw, prev_ww,
                           W_ih, W_hh, b_lstm, W_out, b_out, Ww, bw, Wr, br, out);
}

// round 16
// speedup vs baseline: 1.0024x; 1.0024x over previous
#include <cuda_runtime.h>
#include <math.h>

#define Nn      65536
#define Mm      256
#define CTRLD   1024
#define LSTMIN  3072
#define OUTD    2048
#define EPSF    1e-8f

#define PGRID   592            // 4 blocks/SM * 148 SMs
#define PBLK    256
#define NWARP   8
#define MAXRB   128

// ---------------- scratch ----------------
__device__ float g_mem[(size_t)Nn * Mm];
__device__ float g_simw[Nn], g_simr[Nn];
__device__ float g_gates[3 * CTRLD];
__device__ float g_o[4 * 1036];
__device__ float g_kw[4 * Mm], g_kr[4 * Mm], g_e[4 * Mm], g_a[4 * Mm];
__device__ float g_sc[80];
__device__ float g_S[32];
__device__ float g_reads[4 * Mm];
__device__ unsigned long long g_barcnt;

// ---------------- helpers ----------------
__device__ __forceinline__ float warpSum(float v) {
#pragma unroll
    for (int o = 16; o; o >>= 1) v += __shfl_down_sync(0xffffffffu, v, o);
    return v;
}
// truncated reductions: 2 levels, partials left in lanes 0..7
__device__ __forceinline__ void warpRed3_8(float& a, float& b, float& c) {
#pragma unroll
    for (int o = 16; o >= 8; o >>= 1) {
        a += __shfl_down_sync(0xffffffffu, a, o);
        b += __shfl_down_sync(0xffffffffu, b, o);
        c += __shfl_down_sync(0xffffffffu, c, o);
    }
}
__device__ __forceinline__ void warpRed2_8(float& a, float& b) {
#pragma unroll
    for (int o = 16; o >= 8; o >>= 1) {
        a += __shfl_down_sync(0xffffffffu, a, o);
        b += __shfl_down_sync(0xffffffffu, b, o);
    }
}
__device__ __forceinline__ float blockSumB(float v) {
    __shared__ float sh[8];
    int lane = threadIdx.x & 31, wid = threadIdx.x >> 5;
    v = warpSum(v);
    if (lane == 0) sh[wid] = v;
    __syncthreads();
    float s = sh[0] + sh[1] + sh[2] + sh[3] + sh[4] + sh[5] + sh[6] + sh[7];
    __syncthreads();
    return s;
}
__device__ __forceinline__ float sigmoidf(float x) { return 1.f / (1.f + expf(-x)); }
__device__ __forceinline__ float softplusf(float x) {
    return x > 0.f ? x + log1pf(expf(-x)) : log1pf(expf(x));
}
__device__ __forceinline__ float dot4(float4 a, float4 b) {
    return a.x * b.x + a.y * b.y + a.z * b.z + a.w * b.w;
}
__device__ __forceinline__ float4 apply4(float4 m, float w, float4 e, float4 a) {
    float4 r;
    r.x = m.x * (1.f - w * e.x) + w * a.x;
    r.y = m.y * (1.f - w * e.y) + w * a.y;
    r.z = m.z * (1.f - w * e.z) + w * a.z;
    r.w = m.w * (1.f - w * e.w) + w * a.w;
    return r;
}
__device__ __forceinline__ int rowStart(int b) {
    return (int)(((long long)b << 16) / PGRID);
}
__device__ __forceinline__ void gridbar(int idx) {
    __syncthreads();
    if (threadIdx.x == 0) {
        __threadfence();
        atomicAdd(&g_barcnt, 1ULL);
        unsigned long long target = (unsigned long long)idx * PGRID;
        while (*(volatile unsigned long long*)&g_barcnt < target) __nanosleep(32);
        __threadfence();
    }
    __syncthreads();
}
__device__ __forceinline__ void cpa16(void* sdst, const void* gsrc) {
    unsigned s = (unsigned)__cvta_generic_to_shared(sdst);
    asm volatile("cp.async.cg.shared.global [%0], [%1], 16;" :: "r"(s), "l"(gsrc));
}
#define CPA_COMMIT() asm volatile("cp.async.commit_group;")
#define CPA_WAIT1()  asm volatile("cp.async.wait_group 1;")
#define CPA_WAIT0()  asm volatile("cp.async.wait_group 0;")

// non-hoistable 128-bit shared load (keeps vectors out of the register file)
__device__ __forceinline__ float4 lds128v(const void* p) {
    float4 v; unsigned a = (unsigned)__cvta_generic_to_shared(p);
    asm volatile("ld.shared.v4.f32 {%0,%1,%2,%3}, [%4];"
                 : "=f"(v.x), "=f"(v.y), "=f"(v.z), "=f"(v.w) : "r"(a));
    return v;
}
// sum the 8 partials for row t from a padded [row][9] array
__device__ __forceinline__ float sum8(const float* arr, int t) {
    const float* p = arr + t * 9;
    return ((p[0] + p[1]) + (p[2] + p[3])) + ((p[4] + p[5]) + (p[6] + p[7]));
}

// ---------------- init ----------------
__global__ void k_init() {
    int t = threadIdx.x;
    if (t == 0) g_barcnt = 0ULL;
    if (t < 32) g_S[t] = 0.f;
    g_reads[t] = 0.f;              // blockDim = 1024
}

// ---------------- the one persistent kernel ----------------
__global__ void __launch_bounds__(PBLK, 4) k_all(
    const float* __restrict__ x, const float* __restrict__ prev_reads,
    const float* __restrict__ prev_h, const float* __restrict__ prev_c,
    const float* __restrict__ mem_in,
    const float* __restrict__ prev_rw, const float* __restrict__ prev_ww,
    const float* __restrict__ W_ih, const float* __restrict__ W_hh,
    const float* __restrict__ b_lstm,
    const float* __restrict__ W_out, const float* __restrict__ b_out,
    const float* __restrict__ Ww, const float* __restrict__ bw,
    const float* __restrict__ Wr, const float* __restrict__ br,
    float* __restrict__ out) {
    __shared__ float4 s_stage[NWARP][2][64];        // 16KB 2-deep cp.async ring
    __shared__ float  s_buf[1024];
    __shared__ float  s_vec[512];                   // staged kr/kw for U1
    __shared__ float  s_dr8[MAXRB * 9], s_ss8[MAXRB * 9], s_dw8[MAXRB * 9];
    __shared__ float  s_wshr[MAXRB], s_wshw[MAXRB];
    __shared__ float  s_w0[MAXRB], s_w1[MAXRB], s_wb[MAXRB];
    __shared__ float  s_wn2[MAXRB], s_wn3[MAXRB];
    __shared__ float  s_acc[Mm];
    const int b = blockIdx.x, t = threadIdx.x, lane = t & 31, wrp = t >> 5;
    const int rs = rowStart(b), re = rowStart(b + 1);
    const int nb = re - rs;
    const int gw = b * NWARP + wrp;

#define PIPE_ISSUE(SRC, RI, BI) do {                                              \
        if ((RI) < re) {                                                          \
            const float4* _row = (const float4*)((SRC) + (size_t)(RI) * Mm);      \
            cpa16(&s_stage[wrp][BI][lane], _row + lane);                          \
            cpa16(&s_stage[wrp][BI][lane + 32], _row + lane + 32);                \
        }                                                                         \
        CPA_COMMIT();                                                             \
    } while (0)

    // ===== phase 1: LSTM gates (warps 0..3071) + mem0 L2 prefetch (rest) =====
    {
        float4* si4 = (float4*)s_stage;             // 16KB staging inside ring
        for (int j = t; j < 512; j += PBLK) si4[j] = ((const float4*)x)[j];
        si4[512 + t] = ((const float4*)prev_reads)[t];
        si4[768 + t] = ((const float4*)prev_h)[t];
        __syncthreads();
        if (gw < 3072) {
            const float4* wa = (const float4*)(W_ih + (size_t)gw * LSTMIN);
            const float4* wh = (const float4*)(W_hh + (size_t)gw * CTRLD);
            float s = 0.f;
#pragma unroll 8
            for (int j = lane; j < 768; j += 32) s += dot4(wa[j], si4[j]);
#pragma unroll 8
            for (int j = lane; j < 256; j += 32) s += dot4(wh[j], si4[768 + j]);
            s = warpSum(s);
            if (lane == 0) g_gates[gw] = s + b_lstm[gw];
        } else {
            int pw = gw - 3072;
            const int TOT4 = Nn * Mm / 4;
            int start = pw * 2522;
            int end = start + 2522; if (end > TOT4) end = TOT4;
            const float4* p = (const float4*)mem_in;
            float acc = 0.f;
            for (int i = start + lane; i < end; i += 32) { float4 v = __ldcg(p + i); acc += v.x + v.w; }
            if (acc == -1.2345e+37f) g_sc[79] = acc;   // never true; defeats DCE
        }
    }
    gridbar(1);

    // ===== phase 2: ctrl (per-block) + head FC GEMV =====
    {
        for (int j = t; j < CTRLD; j += PBLK) {
            float ig = __ldcg(&g_gates[j]);
            float fg = __ldcg(&g_gates[CTRLD + j]);
            float gg = __ldcg(&g_gates[2 * CTRLD + j]);
            s_buf[j] = sigmoidf(fg) * prev_c[j] + sigmoidf(ig) * tanhf(gg);
        }
        __syncthreads();
        if (gw < 4144) {
            const float4* c4 = (const float4*)s_buf;
            int hd = gw / 1036, k = gw % 1036;
            const float* wrow; float bias;
            if (k < 774) { wrow = Ww + ((size_t)hd * 774 + k) * CTRLD; bias = bw[hd * 774 + k]; }
            else { int kk = k - 774; wrow = Wr + ((size_t)hd * 262 + kk) * CTRLD; bias = br[hd * 262 + kk]; }
            const float4* w4 = (const float4*)wrow;
            float s = 0.f;
#pragma unroll 8
            for (int j = lane; j < 256; j += 32) s += dot4(w4[j], c4[j]);
            s = warpSum(s);
            if (lane == 0) g_o[gw] = s + bias;
        }
    }
    gridbar(2);
    PIPE_ISSUE(mem_in, rs + wrp, 0);                // pass0 prefetch (overlaps derive)

    // ===== phase 3: derive (blocks 0-7) + local head0 key + pass0 sims =====
    {
        if (b < 8) {
            int hh = b >> 1, role = b & 1;
            const float* o = g_o + hh * 1036 + (role ? 774 : 0);
            float kv = tanhf(__ldcg(&o[t]));
            (role ? g_kr : g_kw)[hh * Mm + t] = kv;
            if (!role) {
                g_e[hh * Mm + t] = sigmoidf(__ldcg(&o[262 + t]));
                g_a[hh * Mm + t] = tanhf(__ldcg(&o[518 + t]));
            }
            float ss = blockSumB(kv * kv);
            if (t == 0) {
                float* sc = g_sc + b * 8;
                sc[0] = softplusf(__ldcg(&o[256]));
                sc[1] = sigmoidf(__ldcg(&o[257]));
                float s0 = __ldcg(&o[258]), s1 = __ldcg(&o[259]), s2 = __ldcg(&o[260]);
                float mx = fmaxf(s0, fmaxf(s1, s2));
                float e0 = expf(s0 - mx), e1 = expf(s1 - mx), e2 = expf(s2 - mx);
                float es = e0 + e1 + e2;
                sc[2] = e0 / es; sc[3] = e1 / es; sc[4] = e2 / es;
                sc[5] = 1.f + softplusf(__ldcg(&o[261]));
                sc[6] = sqrtf(ss);
            }
        }
        __syncthreads();
        float kv = tanhf(__ldcg(&g_o[t < 256 ? t : 0]));
        if (t < 256) s_buf[t] = kv;
        float kn = sqrtf(blockSumB(t < 256 ? kv * kv : 0.f));
        float beta0 = softplusf(__ldcg(&g_o[256]));
        __syncthreads();
        float4 k0 = ((const float4*)s_buf)[lane], k1 = ((const float4*)s_buf)[lane + 32];
        int bi = 0;
        for (int r = rs + wrp; r < re; r += NWARP) {
            PIPE_ISSUE(mem_in, r + NWARP, bi ^ 1);
            CPA_WAIT1();
            float4 m0 = s_stage[wrp][bi][lane], m1 = s_stage[wrp][bi][lane + 32];
            float dot = dot4(m0, k0) + dot4(m1, k1);
            float ss2 = dot4(m0, m0) + dot4(m1, m1);
            warpRed2_8(dot, ss2);
            if (lane < 8) { s_dr8[(r - rs) * 9 + lane] = dot; s_ss8[(r - rs) * 9 + lane] = ss2; }
            bi ^= 1;
        }
        CPA_WAIT0();
        __syncthreads();
        float ess = 0.f;
        if (t < nb) {
            float dot = sum8(s_dr8, t), ss2 = sum8(s_ss8, t);
            float sim = __fdividef(dot, sqrtf(ss2) * kn + EPSF);
            g_simw[rs + t] = sim;
            ess = __expf(beta0 * sim);
        }
        float s = blockSumB(ess);
        if (t == 0) atomicAdd(&g_S[0], s);
    }
    gridbar(3);

#define ADDR_PHASE(HR, HW)                                                          \
    {                                                                               \
        float sumr = 0.f, sumw = 0.f;                                               \
        if (t < nb) {                                                               \
            int i = rs + t;                                                         \
            int ip = (i + 1) & (Nn - 1), im = (i - 1) & (Nn - 1);                   \
            if ((HR) >= 0) {                                                        \
                const float* sc = g_sc + ((HR) * 2 + 1) * 8;                        \
                float beta = __ldcg(&sc[0]), gg = __ldcg(&sc[1]);                   \
                float c0 = __ldcg(&sc[2]), c1 = __ldcg(&sc[3]), c2 = __ldcg(&sc[4]);\
                float gamma = __ldcg(&sc[5]);                                       \
                float gS = __fdividef(gg, __ldcg(&g_S[(HR) * 4 + 2]));              \
                float om = 1.f - gg;                                                \
                const float* pw = prev_rw + (size_t)(HR) * Nn;                      \
                float wgp = gS * __expf(beta * __ldcg(&g_simr[ip])) + om * pw[ip];  \
                float wgc = gS * __expf(beta * __ldcg(&g_simr[i]))  + om * pw[i];   \
                float wgm = gS * __expf(beta * __ldcg(&g_simr[im])) + om * pw[im];  \
                float ws = c0 * wgp + c1 * wgc + c2 * wgm;                          \
                float wsh = __powf(fmaxf(ws, 1e-12f), gamma);                       \
                s_wshr[t] = wsh; sumr = wsh;                                        \
            }                                                                       \
            if ((HW) >= 0) {                                                        \
                const float* sc = g_sc + ((HW) * 2) * 8;                            \
                float beta = __ldcg(&sc[0]), gg = __ldcg(&sc[1]);                   \
                float c0 = __ldcg(&sc[2]), c1 = __ldcg(&sc[3]), c2 = __ldcg(&sc[4]);\
                float gamma = __ldcg(&sc[5]);                                       \
                float gS = __fdividef(gg, __ldcg(&g_S[(HW) * 4 + 0]));              \
                float om = 1.f - gg;                                                \
                const float* pw = prev_ww + (size_t)(HW) * Nn;                      \
                float wgp = gS * __expf(beta * __ldcg(&g_simw[ip])) + om * pw[ip];  \
                float wgc = gS * __expf(beta * __ldcg(&g_simw[i]))  + om * pw[i];   \
                float wgm = gS * __expf(beta * __ldcg(&g_simw[im])) + om * pw[im];  \
                float ws = c0 * wgp + c1 * wgc + c2 * wgm;                          \
                float wsh = __powf(fmaxf(ws, 1e-12f), gamma);                       \
                s_wshw[t] = wsh; sumw = wsh;                                        \
            }                                                                       \
        }                                                                           \
        float sr = blockSumB(sumr);                                                 \
        float sw = blockSumB(sumw);                                                 \
        if (t == 0) {                                                               \
            if ((HR) >= 0) atomicAdd(&g_S[(HR) * 4 + 3], sr);                       \
            if ((HW) >= 0) atomicAdd(&g_S[(HW) * 4 + 1], sw);                       \
        }                                                                           \
    }

    ADDR_PHASE(-1, 0);
    PIPE_ISSUE(mem_in, rs + wrp, 0);                // U0 prefetch (overlaps barrier)
    gridbar(4);

    // ===== U0: read mem0; NO write; sims kr0 / kw1 on n0 = apply(m0, w0) =====
    {
        if (t < nb) s_w0[t] = s_wshw[t] / (__ldcg(&g_S[1]) + EPSF);
        __syncthreads();
        float4 e0 = __ldcg((const float4*)g_e + lane),        e1 = __ldcg((const float4*)g_e + lane + 32);
        float4 a0 = __ldcg((const float4*)g_a + lane),        a1 = __ldcg((const float4*)g_a + lane + 32);
        float4 kr0 = __ldcg((const float4*)g_kr + lane),      kr1 = __ldcg((const float4*)g_kr + lane + 32);
        float4 kw0 = __ldcg((const float4*)(g_kw + Mm) + lane), kw1 = __ldcg((const float4*)(g_kw + Mm) + lane + 32);
        int bi = 0;
        for (int r = rs + wrp; r < re; r += NWARP) {
            PIPE_ISSUE(mem_in, r + NWARP, bi ^ 1);
            CPA_WAIT1();
            float4 m0 = s_stage[wrp][bi][lane], m1 = s_stage[wrp][bi][lane + 32];
            float w = s_w0[r - rs];
            float4 n0 = apply4(m0, w, e0, a0), n1 = apply4(m1, w, e1, a1);
            float dr = dot4(n0, kr0) + dot4(n1, kr1);
            float ss = dot4(n0, n0) + dot4(n1, n1);
            float dw = dot4(n0, kw0) + dot4(n1, kw1);
            warpRed3_8(dr, ss, dw);
            if (lane < 8) {
                int o9 = (r - rs) * 9 + lane;
                s_dr8[o9] = dr; s_ss8[o9] = ss; s_dw8[o9] = dw;
            }
            bi ^= 1;
        }
        CPA_WAIT0();
        __syncthreads();
        float er = 0.f, ew = 0.f;
        if (t < nb) {
            float nrm = sqrtf(sum8(s_ss8, t));
            float beta_r = __ldcg(&g_sc[1 * 8 + 0]), kn_r = __ldcg(&g_sc[1 * 8 + 6]);
            float beta_w = __ldcg(&g_sc[2 * 8 + 0]), kn_w = __ldcg(&g_sc[2 * 8 + 6]);
            float simr = __fdividef(sum8(s_dr8, t), nrm * kn_r + EPSF); g_simr[rs + t] = simr; er = __expf(beta_r * simr);
            float simw = __fdividef(sum8(s_dw8, t), nrm * kn_w + EPSF); g_simw[rs + t] = simw; ew = __expf(beta_w * simw);
        }
        float sr = blockSumB(er), sw = blockSumB(ew);
        if (t == 0) { atomicAdd(&g_S[2], sr); atomicAdd(&g_S[4], sw); }
    }
    gridbar(5);
    ADDR_PHASE(0, 1);
    PIPE_ISSUE(mem_in, rs + wrp, 0);                // U1 prefetch
    gridbar(6);

    // ===== U1: read mem0; recompute m1 = apply(m0,w0); reads[0] on m1;
    //           write mem2 = apply(m1,w1); sims kr1 / kw2 on mem2 =====
    {
        if (t < nb) {
            s_w1[t] = s_wshw[t] / (__ldcg(&g_S[5]) + EPSF);
            s_wb[t] = s_wshr[t] / (__ldcg(&g_S[3]) + EPSF);
        }
        s_acc[t] = 0.f;
        if (t < 256) { s_vec[t] = __ldcg(&g_kr[Mm + t]); s_vec[256 + t] = __ldcg(&g_kw[2 * Mm + t]); }
        __syncthreads();
        float4 e00 = __ldcg((const float4*)g_e + lane),        e01 = __ldcg((const float4*)g_e + lane + 32);
        float4 a00 = __ldcg((const float4*)g_a + lane),        a01 = __ldcg((const float4*)g_a + lane + 32);
        float4 e10 = __ldcg((const float4*)(g_e + Mm) + lane),  e11 = __ldcg((const float4*)(g_e + Mm) + lane + 32);
        float4 a10 = __ldcg((const float4*)(g_a + Mm) + lane),  a11 = __ldcg((const float4*)(g_a + Mm) + lane + 32);
        const float4* v4 = (const float4*)s_vec;
        float4 racc0 = make_float4(0, 0, 0, 0), racc1 = make_float4(0, 0, 0, 0);
        int bi = 0;
        for (int r = rs + wrp; r < re; r += NWARP) {
            PIPE_ISSUE(mem_in, r + NWARP, bi ^ 1);
            CPA_WAIT1();
            float4 m0 = s_stage[wrp][bi][lane], m1 = s_stage[wrp][bi][lane + 32];
            float w0 = s_w0[r - rs], w1 = s_w1[r - rs], wp = s_wb[r - rs];
            float4 p0 = apply4(m0, w0, e00, a00), p1 = apply4(m1, w0, e01, a01);   // mem1 row
            racc0.x += wp * p0.x; racc0.y += wp * p0.y; racc0.z += wp * p0.z; racc0.w += wp * p0.w;
            racc1.x += wp * p1.x; racc1.y += wp * p1.y; racc1.z += wp * p1.z; racc1.w += wp * p1.w;
            float4 n0 = apply4(p0, w1, e10, a10), n1 = apply4(p1, w1, e11, a11);   // mem2 row
            float4* dst = (float4*)(g_mem + (size_t)r * Mm);
            dst[lane] = n0; dst[lane + 32] = n1;
            float4 krA = lds128v(v4 + lane), krB = lds128v(v4 + lane + 32);
            float4 kwA = lds128v(v4 + 64 + lane), kwB = lds128v(v4 + 64 + lane + 32);
            float dr = dot4(n0, krA) + dot4(n1, krB);
            float ss = dot4(n0, n0) + dot4(n1, n1);
            float dw = dot4(n0, kwA) + dot4(n1, kwB);
            warpRed3_8(dr, ss, dw);
            if (lane < 8) {
                int o9 = (r - rs) * 9 + lane;
                s_dr8[o9] = dr; s_ss8[o9] = ss; s_dw8[o9] = dw;
            }
            bi ^= 1;
        }
        CPA_WAIT0();
        atomicAdd(&s_acc[4 * lane + 0], racc0.x); atomicAdd(&s_acc[4 * lane + 1], racc0.y);
        atomicAdd(&s_acc[4 * lane + 2], racc0.z); atomicAdd(&s_acc[4 * lane + 3], racc0.w);
        atomicAdd(&s_acc[128 + 4 * lane + 0], racc1.x); atomicAdd(&s_acc[128 + 4 * lane + 1], racc1.y);
        atomicAdd(&s_acc[128 + 4 * lane + 2], racc1.z); atomicAdd(&s_acc[128 + 4 * lane + 3], racc1.w);
        __syncthreads();
        float er = 0.f, ew = 0.f;
        if (t < nb) {
            float nrm = sqrtf(sum8(s_ss8, t));
            float beta_r = __ldcg(&g_sc[3 * 8 + 0]), kn_r = __ldcg(&g_sc[3 * 8 + 6]);
            float beta_w = __ldcg(&g_sc[4 * 8 + 0]), kn_w = __ldcg(&g_sc[4 * 8 + 6]);
            float simr = __fdividef(sum8(s_dr8, t), nrm * kn_r + EPSF); g_simr[rs + t] = simr; er = __expf(beta_r * simr);
            float simw = __fdividef(sum8(s_dw8, t), nrm * kn_w + EPSF); g_simw[rs + t] = simw; ew = __expf(beta_w * simw);
        }
        float sr = blockSumB(er), sw = blockSumB(ew);
        if (t == 0) { atomicAdd(&g_S[6], sr); atomicAdd(&g_S[8], sw); }
        atomicAdd(&g_reads[0 * Mm + t], s_acc[t]);
    }
    gridbar(7);
    ADDR_PHASE(1, 2);
    PIPE_ISSUE(g_mem, rs + wrp, 0);                 // U2 prefetch (own rows)
    gridbar(8);

    // ===== U2: read mem2; reads[1]; sims kr2 / kw3 on mem3; w2 persisted =====
    {
        if (t < nb) {
            s_wn2[t] = s_wshw[t] / (__ldcg(&g_S[9]) + EPSF);
            s_wb[t]  = s_wshr[t] / (__ldcg(&g_S[7]) + EPSF);
        }
        s_acc[t] = 0.f;
        __syncthreads();
        float4 e0 = __ldcg((const float4*)(g_e + 2 * Mm) + lane),  e1 = __ldcg((const float4*)(g_e + 2 * Mm) + lane + 32);
        float4 a0 = __ldcg((const float4*)(g_a + 2 * Mm) + lane),  a1 = __ldcg((const float4*)(g_a + 2 * Mm) + lane + 32);
        float4 kr0 = __ldcg((const float4*)(g_kr + 2 * Mm) + lane), kr1 = __ldcg((const float4*)(g_kr + 2 * Mm) + lane + 32);
        float4 kw0 = __ldcg((const float4*)(g_kw + 3 * Mm) + lane), kw1 = __ldcg((const float4*)(g_kw + 3 * Mm) + lane + 32);
        float4 racc0 = make_float4(0, 0, 0, 0), racc1 = make_float4(0, 0, 0, 0);
        int bi = 0;
        for (int r = rs + wrp; r < re; r += NWARP) {
            PIPE_ISSUE(g_mem, r + NWARP, bi ^ 1);
            CPA_WAIT1();
            float4 m0 = s_stage[wrp][bi][lane], m1 = s_stage[wrp][bi][lane + 32];
            float w = s_wn2[r - rs], wp = s_wb[r - rs];
            racc0.x += wp * m0.x; racc0.y += wp * m0.y; racc0.z += wp * m0.z; racc0.w += wp * m0.w;
            racc1.x += wp * m1.x; racc1.y += wp * m1.y; racc1.z += wp * m1.z; racc1.w += wp * m1.w;
            float4 n0 = apply4(m0, w, e0, a0), n1 = apply4(m1, w, e1, a1);
            float dr = dot4(n0, kr0) + dot4(n1, kr1);
            float ss = dot4(n0, n0) + dot4(n1, n1);
            float dw = dot4(n0, kw0) + dot4(n1, kw1);
            warpRed3_8(dr, ss, dw);
            if (lane < 8) {
                int o9 = (r - rs) * 9 + lane;
                s_dr8[o9] = dr; s_ss8[o9] = ss; s_dw8[o9] = dw;
            }
            bi ^= 1;
        }
        CPA_WAIT0();
        atomicAdd(&s_acc[4 * lane + 0], racc0.x); atomicAdd(&s_acc[4 * lane + 1], racc0.y);
        atomicAdd(&s_acc[4 * lane + 2], racc0.z); atomicAdd(&s_acc[4 * lane + 3], racc0.w);
        atomicAdd(&s_acc[128 + 4 * lane + 0], racc1.x); atomicAdd(&s_acc[128 + 4 * lane + 1], racc1.y);
        atomicAdd(&s_acc[128 + 4 * lane + 2], racc1.z); atomicAdd(&s_acc[128 + 4 * lane + 3], racc1.w);
        __syncthreads();
        float er = 0.f, ew = 0.f;
        if (t < nb) {
            float nrm = sqrtf(sum8(s_ss8, t));
            float beta_r = __ldcg(&g_sc[5 * 8 + 0]), kn_r = __ldcg(&g_sc[5 * 8 + 6]);
            float beta_w = __ldcg(&g_sc[6 * 8 + 0]), kn_w = __ldcg(&g_sc[6 * 8 + 6]);
            float simr = __fdividef(sum8(s_dr8, t), nrm * kn_r + EPSF); g_simr[rs + t] = simr; er = __expf(beta_r * simr);
            float simw = __fdividef(sum8(s_dw8, t), nrm * kn_w + EPSF); g_simw[rs + t] = simw; ew = __expf(beta_w * simw);
        }
        float sr = blockSumB(er), sw = blockSumB(ew);
        if (t == 0) { atomicAdd(&g_S[10], sr); atomicAdd(&g_S[12], sw); }
        atomicAdd(&g_reads[1 * Mm + t], s_acc[t]);
    }
    gridbar(9);
    ADDR_PHASE(2, 3);
    PIPE_ISSUE(g_mem, rs + wrp, 0);                 // U3 prefetch
    gridbar(10);

    // ===== U3: read mem2; apply w2 then w3; reads[2] on mem3; sim kr3 on mem4 =====
    {
        if (t < nb) {
            s_wn3[t] = s_wshw[t] / (__ldcg(&g_S[13]) + EPSF);
            s_wb[t]  = s_wshr[t] / (__ldcg(&g_S[11]) + EPSF);
        }
        s_acc[t] = 0.f;
        __syncthreads();
        float4 e20 = __ldcg((const float4*)(g_e + 2 * Mm) + lane), e21 = __ldcg((const float4*)(g_e + 2 * Mm) + lane + 32);
        float4 a20 = __ldcg((const float4*)(g_a + 2 * Mm) + lane), a21 = __ldcg((const float4*)(g_a + 2 * Mm) + lane + 32);
        float4 e30 = __ldcg((const float4*)(g_e + 3 * Mm) + lane), e31 = __ldcg((const float4*)(g_e + 3 * Mm) + lane + 32);
        float4 a30 = __ldcg((const float4*)(g_a + 3 * Mm) + lane), a31 = __ldcg((const float4*)(g_a + 3 * Mm) + lane + 32);
        float4 kr0 = __ldcg((const float4*)(g_kr + 3 * Mm) + lane), kr1 = __ldcg((const float4*)(g_kr + 3 * Mm) + lane + 32);
        float4 racc0 = make_float4(0, 0, 0, 0), racc1 = make_float4(0, 0, 0, 0);
        int bi = 0;
        for (int r = rs + wrp; r < re; r += NWARP) {
            PIPE_ISSUE(g_mem, r + NWARP, bi ^ 1);
            CPA_WAIT1();
            float4 m0 = s_stage[wrp][bi][lane], m1 = s_stage[wrp][bi][lane + 32];
            float w2 = s_wn2[r - rs], w3 = s_wn3[r - rs], wp = s_wb[r - rs];
            m0 = apply4(m0, w2, e20, a20); m1 = apply4(m1, w2, e21, a21);   // mem3
            racc0.x += wp * m0.x; racc0.y += wp * m0.y; racc0.z += wp * m0.z; racc0.w += wp * m0.w;
            racc1.x += wp * m1.x; racc1.y += wp * m1.y; racc1.z += wp * m1.z; racc1.w += wp * m1.w;
            float4 n0 = apply4(m0, w3, e30, a30), n1 = apply4(m1, w3, e31, a31);  // mem4
            float dr = dot4(n0, kr0) + dot4(n1, kr1);
            float ss = dot4(n0, n0) + dot4(n1, n1);
            warpRed2_8(dr, ss);
            if (lane < 8) {
                int o9 = (r - rs) * 9 + lane;
                s_dr8[o9] = dr; s_ss8[o9] = ss;
            }
            bi ^= 1;
        }
        CPA_WAIT0();
        atomicAdd(&s_acc[4 * lane + 0], racc0.x); atomicAdd(&s_acc[4 * lane + 1], racc0.y);
        atomicAdd(&s_acc[4 * lane + 2], racc0.z); atomicAdd(&s_acc[4 * lane + 3], racc0.w);
        atomicAdd(&s_acc[128 + 4 * lane + 0], racc1.x); atomicAdd(&s_acc[128 + 4 * lane + 1], racc1.y);
        atomicAdd(&s_acc[128 + 4 * lane + 2], racc1.z); atomicAdd(&s_acc[128 + 4 * lane + 3], racc1.w);
        __syncthreads();
        float er = 0.f;
        if (t < nb) {
            float beta_r = __ldcg(&g_sc[7 * 8 + 0]), kn_r = __ldcg(&g_sc[7 * 8 + 6]);
            float simr = __fdividef(sum8(s_dr8, t), sqrtf(sum8(s_ss8, t)) * kn_r + EPSF);
            g_simr[rs + t] = simr; er = __expf(beta_r * simr);
        }
        float sr = blockSumB(er);
        if (t == 0) atomicAdd(&g_S[14], sr);
        atomicAdd(&g_reads[2 * Mm + t], s_acc[t]);
    }
    gridbar(11);
    ADDR_PHASE(3, -1);
    PIPE_ISSUE(g_mem, rs + wrp, 0);                 // FINAL prefetch
    gridbar(12);

    // ===== FINAL: reads[3] on mem4 = apply(w2, w3) over mem2 =====
    {
        if (t < nb) s_wb[t] = s_wshr[t] / (__ldcg(&g_S[15]) + EPSF);
        s_acc[t] = 0.f;
        __syncthreads();
        float4 e20 = __ldcg((const float4*)(g_e + 2 * Mm) + lane), e21 = __ldcg((const float4*)(g_e + 2 * Mm) + lane + 32);
        float4 a20 = __ldcg((const float4*)(g_a + 2 * Mm) + lane), a21 = __ldcg((const float4*)(g_a + 2 * Mm) + lane + 32);
        float4 e30 = __ldcg((const float4*)(g_e + 3 * Mm) + lane), e31 = __ldcg((const float4*)(g_e + 3 * Mm) + lane + 32);
        float4 a30 = __ldcg((const float4*)(g_a + 3 * Mm) + lane), a31 = __ldcg((const float4*)(g_a + 3 * Mm) + lane + 32);
        float4 racc0 = make_float4(0, 0, 0, 0), racc1 = make_float4(0, 0, 0, 0);
        int bi = 0;
        for (int r = rs + wrp; r < re; r += NWARP) {
            PIPE_ISSUE(g_mem, r + NWARP, bi ^ 1);
            CPA_WAIT1();
            float4 m0 = s_stage[wrp][bi][lane], m1 = s_stage[wrp][bi][lane + 32];
            float w2 = s_wn2[r - rs], w3 = s_wn3[r - rs], wr = s_wb[r - rs];
            m0 = apply4(m0, w2, e20, a20); m1 = apply4(m1, w2, e21, a21);
            m0 = apply4(m0, w3, e30, a30); m1 = apply4(m1, w3, e31, a31);
            racc0.x += wr * m0.x; racc0.y += wr * m0.y; racc0.z += wr * m0.z; racc0.w += wr * m0.w;
            racc1.x += wr * m1.x; racc1.y += wr * m1.y; racc1.z += wr * m1.z; racc1.w += wr * m1.w;
            bi ^= 1;
        }
        CPA_WAIT0();
        atomicAdd(&s_acc[4 * lane + 0], racc0.x); atomicAdd(&s_acc[4 * lane + 1], racc0.y);
        atomicAdd(&s_acc[4 * lane + 2], racc0.z); atomicAdd(&s_acc[4 * lane + 3], racc0.w);
        atomicAdd(&s_acc[128 + 4 * lane + 0], racc1.x); atomicAdd(&s_acc[128 + 4 * lane + 1], racc1.y);
        atomicAdd(&s_acc[128 + 4 * lane + 2], racc1.z); atomicAdd(&s_acc[128 + 4 * lane + 3], racc1.w);
        __syncthreads();
        atomicAdd(&g_reads[3 * Mm + t], s_acc[t]);
    }
    gridbar(13);

    // ===== OUT: warp-per-row (blocks 0..255) =====
    if (b < 256) {
        for (int j = t; j < CTRLD; j += PBLK) s_buf[j] = __ldcg(&g_reads[j]);
        __syncthreads();
        int row = b * 8 + wrp;
        const float4* w4 = (const float4*)(W_out + (size_t)row * CTRLD);
        const float4* r4 = (const float4*)s_buf;
        float s = 0.f;
#pragma unroll 8
        for (int j = lane; j < 256; j += 32) s += dot4(w4[j], r4[j]);
        s = warpSum(s);
        if (lane == 0) out[row] = s + b_out[row];
    }
}

// ---------------- launch ----------------
extern "C" void kernel_launch(void* const* d_in, const int* in_sizes, int n_in,
                              void* d_out, int out_size) {
    const float* x          = (const float*)d_in[0];
    const float* prev_reads = (const float*)d_in[1];
    const float* prev_h     = (const float*)d_in[2];
    const float* prev_c     = (const float*)d_in[3];
    const float* memory     = (const float*)d_in[4];
    const float* prev_rw    = (const float*)d_in[5];
    const float* prev_ww    = (const float*)d_in[6];
    const float* W_ih       = (const float*)d_in[7];
    const float* W_hh       = (const float*)d_in[8];
    const float* b_lstm     = (const float*)d_in[9];
    const float* W_out      = (const float*)d_in[10];
    const float* b_out      = (const float*)d_in[11];
    const float* Ww         = (const float*)d_in[12];
    const float* bw         = (const float*)d_in[13];
    const float* Wr         = (const float*)d_in[14];
    const float* br         = (const float*)d_in[15];
    float* out = (float*)d_out;

    k_init<<<1, 1024>>>();
    k_all<<<PGRID, PBLK>>>(x, prev_reads, prev_h, prev_c, memory, prev_rw, prev_ww,
                           W_ih, W_hh, b_lstm, W_out, b_out, Ww, bw, Wr, br, out);
}

// round 17
// speedup vs baseline: 1.0111x; 1.0087x over previous
#include <cuda_runtime.h>
#include <math.h>

#define Nn      65536
#define Mm      256
#define CTRLD   1024
#define LSTMIN  3072
#define OUTD    2048
#define EPSF    1e-8f

#define PGRID   592            // 4 blocks/SM * 148 SMs
#define PBLK    256
#define NWARP   8
#define MAXRB   128

// ---------------- scratch ----------------
__device__ float g_mem[(size_t)Nn * Mm];
__device__ float g_simw[Nn], g_simr[Nn];
__device__ float g_gates[3 * CTRLD];
__device__ float g_o[4 * 1036];
__device__ float g_kw[4 * Mm], g_kr[4 * Mm], g_e[4 * Mm], g_a[4 * Mm];
__device__ float g_sc[80];
__device__ float g_S[32];
__device__ float g_reads[4 * Mm];
__device__ unsigned long long g_barcnt;

// ---------------- helpers ----------------
__device__ __forceinline__ float warpSum(float v) {
#pragma unroll
    for (int o = 16; o; o >>= 1) v += __shfl_down_sync(0xffffffffu, v, o);
    return v;
}
__device__ __forceinline__ void warpSum3(float& a, float& b, float& c) {
#pragma unroll
    for (int o = 16; o; o >>= 1) {
        a += __shfl_down_sync(0xffffffffu, a, o);
        b += __shfl_down_sync(0xffffffffu, b, o);
        c += __shfl_down_sync(0xffffffffu, c, o);
    }
}
__device__ __forceinline__ void warpSum2(float& a, float& b) {
#pragma unroll
    for (int o = 16; o; o >>= 1) {
        a += __shfl_down_sync(0xffffffffu, a, o);
        b += __shfl_down_sync(0xffffffffu, b, o);
    }
}
__device__ __forceinline__ float blockSumB(float v) {
    __shared__ float sh[8];
    int lane = threadIdx.x & 31, wid = threadIdx.x >> 5;
    v = warpSum(v);
    if (lane == 0) sh[wid] = v;
    __syncthreads();
    float s = sh[0] + sh[1] + sh[2] + sh[3] + sh[4] + sh[5] + sh[6] + sh[7];
    __syncthreads();
    return s;
}
__device__ __forceinline__ float sigmoidf(float x) { return 1.f / (1.f + expf(-x)); }
__device__ __forceinline__ float softplusf(float x) {
    return x > 0.f ? x + log1pf(expf(-x)) : log1pf(expf(x));
}
__device__ __forceinline__ float dot4(float4 a, float4 b) {
    return a.x * b.x + a.y * b.y + a.z * b.z + a.w * b.w;
}
__device__ __forceinline__ float4 apply4(float4 m, float w, float4 e, float4 a) {
    float4 r;
    r.x = m.x * (1.f - w * e.x) + w * a.x;
    r.y = m.y * (1.f - w * e.y) + w * a.y;
    r.z = m.z * (1.f - w * e.z) + w * a.z;
    r.w = m.w * (1.f - w * e.w) + w * a.w;
    return r;
}
__device__ __forceinline__ int rowStart(int b) {
    return (int)(((long long)b << 16) / PGRID);
}
__device__ __forceinline__ void gridbar(int idx) {
    __syncthreads();
    if (threadIdx.x == 0) {
        __threadfence();
        atomicAdd(&g_barcnt, 1ULL);
        unsigned long long target = (unsigned long long)idx * PGRID;
        while (*(volatile unsigned long long*)&g_barcnt < target) __nanosleep(32);
        __threadfence();
    }
    __syncthreads();
}
__device__ __forceinline__ void cpa16(void* sdst, const void* gsrc) {
    unsigned s = (unsigned)__cvta_generic_to_shared(sdst);
    asm volatile("cp.async.cg.shared.global [%0], [%1], 16;" :: "r"(s), "l"(gsrc));
}
#define CPA_COMMIT() asm volatile("cp.async.commit_group;")
#define CPA_WAIT1()  asm volatile("cp.async.wait_group 1;")
#define CPA_WAIT0()  asm volatile("cp.async.wait_group 0;")

// non-hoistable 128-bit shared load (keeps vectors out of the register file)
__device__ __forceinline__ float4 lds128v(const void* p) {
    float4 v; unsigned a = (unsigned)__cvta_generic_to_shared(p);
    asm volatile("ld.shared.v4.f32 {%0,%1,%2,%3}, [%4];"
                 : "=f"(v.x), "=f"(v.y), "=f"(v.z), "=f"(v.w) : "r"(a));
    return v;
}

// ---------------- init ----------------
__global__ void k_init() {
    int t = threadIdx.x;
    if (t == 0) g_barcnt = 0ULL;
    if (t < 32) g_S[t] = 0.f;
    g_reads[t] = 0.f;              // blockDim = 1024
}

// ---------------- the one persistent kernel ----------------
__global__ void __launch_bounds__(PBLK, 4) k_all(
    const float* __restrict__ x, const float* __restrict__ prev_reads,
    const float* __restrict__ prev_h, const float* __restrict__ prev_c,
    const float* __restrict__ mem_in,
    const float* __restrict__ prev_rw, const float* __restrict__ prev_ww,
    const float* __restrict__ W_ih, const float* __restrict__ W_hh,
    const float* __restrict__ b_lstm,
    const float* __restrict__ W_out, const float* __restrict__ b_out,
    const float* __restrict__ Ww, const float* __restrict__ bw,
    const float* __restrict__ Wr, const float* __restrict__ br,
    float* __restrict__ out) {
    __shared__ float4 s_stage[NWARP][2][64];        // 16KB 2-deep cp.async ring
    __shared__ float  s_buf[1024];
    __shared__ float  s_vec[512];                   // staged kr/kw for U1
    __shared__ float  s_dr[MAXRB], s_ss[MAXRB], s_dw[MAXRB];
    __shared__ float  s_wshr[MAXRB], s_wshw[MAXRB];
    __shared__ float  s_w0[MAXRB], s_w1[MAXRB], s_wb[MAXRB];
    __shared__ float  s_wn2[MAXRB], s_wn3[MAXRB];
    __shared__ float  s_acc[Mm];
    const int b = blockIdx.x, t = threadIdx.x, lane = t & 31, wrp = t >> 5;
    const int rs = rowStart(b), re = rowStart(b + 1);
    const int nb = re - rs;
    const int gw = b * NWARP + wrp;

#define PIPE_ISSUE(SRC, RI, BI) do {                                              \
        if ((RI) < re) {                                                          \
            const float4* _row = (const float4*)((SRC) + (size_t)(RI) * Mm);      \
            cpa16(&s_stage[wrp][BI][lane], _row + lane);                          \
            cpa16(&s_stage[wrp][BI][lane + 32], _row + lane + 32);                \
        }                                                                         \
        CPA_COMMIT();                                                             \
    } while (0)

    // ===== phase 1: LSTM gates (warps 0..3071) + mem0 L2 prefetch (rest) =====
    {
        float4* si4 = (float4*)s_stage;             // 16KB staging inside ring
        for (int j = t; j < 512; j += PBLK) si4[j] = ((const float4*)x)[j];
        si4[512 + t] = ((const float4*)prev_reads)[t];
        si4[768 + t] = ((const float4*)prev_h)[t];
        __syncthreads();
        if (gw < 3072) {
            const float4* wa = (const float4*)(W_ih + (size_t)gw * LSTMIN);
            const float4* wh = (const float4*)(W_hh + (size_t)gw * CTRLD);
            float s = 0.f;
#pragma unroll 8
            for (int j = lane; j < 768; j += 32) s += dot4(wa[j], si4[j]);
#pragma unroll 8
            for (int j = lane; j < 256; j += 32) s += dot4(wh[j], si4[768 + j]);
            s = warpSum(s);
            if (lane == 0) g_gates[gw] = s + b_lstm[gw];
        } else {
            int pw = gw - 3072;
            const int TOT4 = Nn * Mm / 4;
            int start = pw * 2522;
            int end = start + 2522; if (end > TOT4) end = TOT4;
            const float4* p = (const float4*)mem_in;
            float acc = 0.f;
            for (int i = start + lane; i < end; i += 32) { float4 v = __ldcg(p + i); acc += v.x + v.w; }
            if (acc == -1.2345e+37f) g_sc[79] = acc;   // never true; defeats DCE
        }
    }
    gridbar(1);

    // ===== phase 2: ctrl (per-block) + head FC GEMV =====
    {
        for (int j = t; j < CTRLD; j += PBLK) {
            float ig = __ldcg(&g_gates[j]);
            float fg = __ldcg(&g_gates[CTRLD + j]);
            float gg = __ldcg(&g_gates[2 * CTRLD + j]);
            s_buf[j] = sigmoidf(fg) * prev_c[j] + sigmoidf(ig) * tanhf(gg);
        }
        __syncthreads();
        if (gw < 4144) {
            const float4* c4 = (const float4*)s_buf;
            int hd = gw / 1036, k = gw % 1036;
            const float* wrow; float bias;
            if (k < 774) { wrow = Ww + ((size_t)hd * 774 + k) * CTRLD; bias = bw[hd * 774 + k]; }
            else { int kk = k - 774; wrow = Wr + ((size_t)hd * 262 + kk) * CTRLD; bias = br[hd * 262 + kk]; }
            const float4* w4 = (const float4*)wrow;
            float s = 0.f;
#pragma unroll 8
            for (int j = lane; j < 256; j += 32) s += dot4(w4[j], c4[j]);
            s = warpSum(s);
            if (lane == 0) g_o[gw] = s + bias;
        }
    }
    gridbar(2);
    PIPE_ISSUE(mem_in, rs + wrp, 0);                // pass0 prefetch (overlaps derive)

    // ===== phase 3: derive (blocks 0-7) + local head0 key + pass0 sims =====
    {
        if (b < 8) {
            int hh = b >> 1, role = b & 1;
            const float* o = g_o + hh * 1036 + (role ? 774 : 0);
            float kv = tanhf(__ldcg(&o[t]));
            (role ? g_kr : g_kw)[hh * Mm + t] = kv;
            if (!role) {
                g_e[hh * Mm + t] = sigmoidf(__ldcg(&o[262 + t]));
                g_a[hh * Mm + t] = tanhf(__ldcg(&o[518 + t]));
            }
            float ss = blockSumB(kv * kv);
            if (t == 0) {
                float* sc = g_sc + b * 8;
                sc[0] = softplusf(__ldcg(&o[256]));
                sc[1] = sigmoidf(__ldcg(&o[257]));
                float s0 = __ldcg(&o[258]), s1 = __ldcg(&o[259]), s2 = __ldcg(&o[260]);
                float mx = fmaxf(s0, fmaxf(s1, s2));
                float e0 = expf(s0 - mx), e1 = expf(s1 - mx), e2 = expf(s2 - mx);
                float es = e0 + e1 + e2;
                sc[2] = e0 / es; sc[3] = e1 / es; sc[4] = e2 / es;
                sc[5] = 1.f + softplusf(__ldcg(&o[261]));
                sc[6] = sqrtf(ss);
            }
        }
        __syncthreads();
        float kv = tanhf(__ldcg(&g_o[t < 256 ? t : 0]));
        if (t < 256) s_buf[t] = kv;
        float kn = sqrtf(blockSumB(t < 256 ? kv * kv : 0.f));
        float beta0 = softplusf(__ldcg(&g_o[256]));
        __syncthreads();
        float4 k0 = ((const float4*)s_buf)[lane], k1 = ((const float4*)s_buf)[lane + 32];
        int bi = 0;
        for (int r = rs + wrp; r < re; r += NWARP) {
            PIPE_ISSUE(mem_in, r + NWARP, bi ^ 1);
            CPA_WAIT1();
            float4 m0 = s_stage[wrp][bi][lane], m1 = s_stage[wrp][bi][lane + 32];
            float dot = dot4(m0, k0) + dot4(m1, k1);
            float ss2 = dot4(m0, m0) + dot4(m1, m1);
            warpSum2(dot, ss2);
            if (lane == 0) { s_dr[r - rs] = dot; s_ss[r - rs] = ss2; }
            bi ^= 1;
        }
        CPA_WAIT0();
        __syncthreads();
        float ess = 0.f;
        if (t < nb) {
            float sim = __fdividef(s_dr[t], sqrtf(s_ss[t]) * kn + EPSF);
            g_simw[rs + t] = sim;
            ess = __expf(beta0 * sim);
        }
        float s = blockSumB(ess);
        if (t == 0) atomicAdd(&g_S[0], s);
    }
    gridbar(3);

#define ADDR_PHASE(HR, HW)                                                          \
    {                                                                               \
        float sumr = 0.f, sumw = 0.f;                                               \
        if (t < nb) {                                                               \
            int i = rs + t;                                                         \
            int ip = (i + 1) & (Nn - 1), im = (i - 1) & (Nn - 1);                   \
            if ((HR) >= 0) {                                                        \
                const float* sc = g_sc + ((HR) * 2 + 1) * 8;                        \
                float beta = __ldcg(&sc[0]), gg = __ldcg(&sc[1]);                   \
                float c0 = __ldcg(&sc[2]), c1 = __ldcg(&sc[3]), c2 = __ldcg(&sc[4]);\
                float gamma = __ldcg(&sc[5]);                                       \
                float gS = __fdividef(gg, __ldcg(&g_S[(HR) * 4 + 2]));              \
                float om = 1.f - gg;                                                \
                const float* pw = prev_rw + (size_t)(HR) * Nn;                      \
                float wgp = gS * __expf(beta * __ldcg(&g_simr[ip])) + om * pw[ip];  \
                float wgc = gS * __expf(beta * __ldcg(&g_simr[i]))  + om * pw[i];   \
                float wgm = gS * __expf(beta * __ldcg(&g_simr[im])) + om * pw[im];  \
                float ws = c0 * wgp + c1 * wgc + c2 * wgm;                          \
                float wsh = __powf(fmaxf(ws, 1e-12f), gamma);                       \
                s_wshr[t] = wsh; sumr = wsh;                                        \
            }                                                                       \
            if ((HW) >= 0) {                                                        \
                const float* sc = g_sc + ((HW) * 2) * 8;                            \
                float beta = __ldcg(&sc[0]), gg = __ldcg(&sc[1]);                   \
                float c0 = __ldcg(&sc[2]), c1 = __ldcg(&sc[3]), c2 = __ldcg(&sc[4]);\
                float gamma = __ldcg(&sc[5]);                                       \
                float gS = __fdividef(gg, __ldcg(&g_S[(HW) * 4 + 0]));              \
                float om = 1.f - gg;                                                \
                const float* pw = prev_ww + (size_t)(HW) * Nn;                      \
                float wgp = gS * __expf(beta * __ldcg(&g_simw[ip])) + om * pw[ip];  \
                float wgc = gS * __expf(beta * __ldcg(&g_simw[i]))  + om * pw[i];   \
                float wgm = gS * __expf(beta * __ldcg(&g_simw[im])) + om * pw[im];  \
                float ws = c0 * wgp + c1 * wgc + c2 * wgm;                          \
                float wsh = __powf(fmaxf(ws, 1e-12f), gamma);                       \
                s_wshw[t] = wsh; sumw = wsh;                                        \
            }                                                                       \
        }                                                                           \
        float sr = blockSumB(sumr);                                                 \
        float sw = blockSumB(sumw);                                                 \
        if (t == 0) {                                                               \
            if ((HR) >= 0) atomicAdd(&g_S[(HR) * 4 + 3], sr);                       \
            if ((HW) >= 0) atomicAdd(&g_S[(HW) * 4 + 1], sw);                       \
        }                                                                           \
    }

    ADDR_PHASE(-1, 0);
    PIPE_ISSUE(mem_in, rs + wrp, 0);                // U0 prefetch (overlaps barrier)
    gridbar(4);

    // ===== U0: read mem0; NO write; sims kr0 / kw1 on n0 = apply(m0, w0) =====
    {
        if (t < nb) s_w0[t] = s_wshw[t] / (__ldcg(&g_S[1]) + EPSF);
        __syncthreads();
        float4 e0 = __ldcg((const float4*)g_e + lane),        e1 = __ldcg((const float4*)g_e + lane + 32);
        float4 a0 = __ldcg((const float4*)g_a + lane),        a1 = __ldcg((const float4*)g_a + lane + 32);
        float4 kr0 = __ldcg((const float4*)g_kr + lane),      kr1 = __ldcg((const float4*)g_kr + lane + 32);
        float4 kw0 = __ldcg((const float4*)(g_kw + Mm) + lane), kw1 = __ldcg((const float4*)(g_kw + Mm) + lane + 32);
        int bi = 0;
        for (int r = rs + wrp; r < re; r += NWARP) {
            PIPE_ISSUE(mem_in, r + NWARP, bi ^ 1);
            CPA_WAIT1();
            float4 m0 = s_stage[wrp][bi][lane], m1 = s_stage[wrp][bi][lane + 32];
            float w = s_w0[r - rs];
            float4 n0 = apply4(m0, w, e0, a0), n1 = apply4(m1, w, e1, a1);
            float dr = dot4(n0, kr0) + dot4(n1, kr1);
            float ss = dot4(n0, n0) + dot4(n1, n1);
            float dw = dot4(n0, kw0) + dot4(n1, kw1);
            warpSum3(dr, ss, dw);
            if (lane == 0) { s_dr[r - rs] = dr; s_ss[r - rs] = ss; s_dw[r - rs] = dw; }
            bi ^= 1;
        }
        CPA_WAIT0();
        __syncthreads();
        float er = 0.f, ew = 0.f;
        if (t < nb) {
            float nrm = sqrtf(s_ss[t]);
            float beta_r = __ldcg(&g_sc[1 * 8 + 0]), kn_r = __ldcg(&g_sc[1 * 8 + 6]);
            float beta_w = __ldcg(&g_sc[2 * 8 + 0]), kn_w = __ldcg(&g_sc[2 * 8 + 6]);
            float simr = __fdividef(s_dr[t], nrm * kn_r + EPSF); g_simr[rs + t] = simr; er = __expf(beta_r * simr);
            float simw = __fdividef(s_dw[t], nrm * kn_w + EPSF); g_simw[rs + t] = simw; ew = __expf(beta_w * simw);
        }
        float sr = blockSumB(er), sw = blockSumB(ew);
        if (t == 0) { atomicAdd(&g_S[2], sr); atomicAdd(&g_S[4], sw); }
    }
    gridbar(5);
    ADDR_PHASE(0, 1);
    PIPE_ISSUE(mem_in, rs + wrp, 0);                // U1 prefetch
    gridbar(6);

    // ===== U1: read mem0; recompute m1 = apply(m0,w0); reads[0] on m1;
    //           write mem2 = apply(m1,w1); sims kr1 / kw2 on mem2 =====
    {
        if (t < nb) {
            s_w1[t] = s_wshw[t] / (__ldcg(&g_S[5]) + EPSF);
            s_wb[t] = s_wshr[t] / (__ldcg(&g_S[3]) + EPSF);
        }
        s_acc[t] = 0.f;
        if (t < 256) { s_vec[t] = __ldcg(&g_kr[Mm + t]); s_vec[256 + t] = __ldcg(&g_kw[2 * Mm + t]); }
        __syncthreads();
        float4 e00 = __ldcg((const float4*)g_e + lane),        e01 = __ldcg((const float4*)g_e + lane + 32);
        float4 a00 = __ldcg((const float4*)g_a + lane),        a01 = __ldcg((const float4*)g_a + lane + 32);
        float4 e10 = __ldcg((const float4*)(g_e + Mm) + lane),  e11 = __ldcg((const float4*)(g_e + Mm) + lane + 32);
        float4 a10 = __ldcg((const float4*)(g_a + Mm) + lane),  a11 = __ldcg((const float4*)(g_a + Mm) + lane + 32);
        const float4* v4 = (const float4*)s_vec;
        float4 racc0 = make_float4(0, 0, 0, 0), racc1 = make_float4(0, 0, 0, 0);
        int bi = 0;
        for (int r = rs + wrp; r < re; r += NWARP) {
            PIPE_ISSUE(mem_in, r + NWARP, bi ^ 1);
            CPA_WAIT1();
            float4 m0 = s_stage[wrp][bi][lane], m1 = s_stage[wrp][bi][lane + 32];
            float w0 = s_w0[r - rs], w1 = s_w1[r - rs], wp = s_wb[r - rs];
            float4 p0 = apply4(m0, w0, e00, a00), p1 = apply4(m1, w0, e01, a01);   // mem1 row
            racc0.x += wp * p0.x; racc0.y += wp * p0.y; racc0.z += wp * p0.z; racc0.w += wp * p0.w;
            racc1.x += wp * p1.x; racc1.y += wp * p1.y; racc1.z += wp * p1.z; racc1.w += wp * p1.w;
            float4 n0 = apply4(p0, w1, e10, a10), n1 = apply4(p1, w1, e11, a11);   // mem2 row
            float4* dst = (float4*)(g_mem + (size_t)r * Mm);
            dst[lane] = n0; dst[lane + 32] = n1;
            float4 krA = lds128v(v4 + lane), krB = lds128v(v4 + lane + 32);
            float4 kwA = lds128v(v4 + 64 + lane), kwB = lds128v(v4 + 64 + lane + 32);
            float dr = dot4(n0, krA) + dot4(n1, krB);
            float ss = dot4(n0, n0) + dot4(n1, n1);
            float dw = dot4(n0, kwA) + dot4(n1, kwB);
            warpSum3(dr, ss, dw);
            if (lane == 0) { s_dr[r - rs] = dr; s_ss[r - rs] = ss; s_dw[r - rs] = dw; }
            bi ^= 1;
        }
        CPA_WAIT0();
        atomicAdd(&s_acc[4 * lane + 0], racc0.x); atomicAdd(&s_acc[4 * lane + 1], racc0.y);
        atomicAdd(&s_acc[4 * lane + 2], racc0.z); atomicAdd(&s_acc[4 * lane + 3], racc0.w);
        atomicAdd(&s_acc[128 + 4 * lane + 0], racc1.x); atomicAdd(&s_acc[128 + 4 * lane + 1], racc1.y);
        atomicAdd(&s_acc[128 + 4 * lane + 2], racc1.z); atomicAdd(&s_acc[128 + 4 * lane + 3], racc1.w);
        __syncthreads();
        float er = 0.f, ew = 0.f;
        if (t < nb) {
            float nrm = sqrtf(s_ss[t]);
            float beta_r = __ldcg(&g_sc[3 * 8 + 0]), kn_r = __ldcg(&g_sc[3 * 8 + 6]);
            float beta_w = __ldcg(&g_sc[4 * 8 + 0]), kn_w = __ldcg(&g_sc[4 * 8 + 6]);
            float simr = __fdividef(s_dr[t], nrm * kn_r + EPSF); g_simr[rs + t] = simr; er = __expf(beta_r * simr);
            float simw = __fdividef(s_dw[t], nrm * kn_w + EPSF); g_simw[rs + t] = simw; ew = __expf(beta_w * simw);
        }
        float sr = blockSumB(er), sw = blockSumB(ew);
        if (t == 0) { atomicAdd(&g_S[6], sr); atomicAdd(&g_S[8], sw); }
        atomicAdd(&g_reads[0 * Mm + t], s_acc[t]);
    }
    gridbar(7);
    ADDR_PHASE(1, 2);
    PIPE_ISSUE(g_mem, rs + wrp, 0);                 // U2 prefetch (own rows)
    gridbar(8);

    // ===== U2: read mem2; reads[1]; sims kr2 / kw3 on mem3; w2 persisted =====
    {
        if (t < nb) {
            s_wn2[t] = s_wshw[t] / (__ldcg(&g_S[9]) + EPSF);
            s_wb[t]  = s_wshr[t] / (__ldcg(&g_S[7]) + EPSF);
        }
        s_acc[t] = 0.f;
        __syncthreads();
        float4 e0 = __ldcg((const float4*)(g_e + 2 * Mm) + lane),  e1 = __ldcg((const float4*)(g_e + 2 * Mm) + lane + 32);
        float4 a0 = __ldcg((const float4*)(g_a + 2 * Mm) + lane),  a1 = __ldcg((const float4*)(g_a + 2 * Mm) + lane + 32);
        float4 kr0 = __ldcg((const float4*)(g_kr + 2 * Mm) + lane), kr1 = __ldcg((const float4*)(g_kr + 2 * Mm) + lane + 32);
        float4 kw0 = __ldcg((const float4*)(g_kw + 3 * Mm) + lane), kw1 = __ldcg((const float4*)(g_kw + 3 * Mm) + lane + 32);
        float4 racc0 = make_float4(0, 0, 0, 0), racc1 = make_float4(0, 0, 0, 0);
        int bi = 0;
        for (int r = rs + wrp; r < re; r += NWARP) {
            PIPE_ISSUE(g_mem, r + NWARP, bi ^ 1);
            CPA_WAIT1();
            float4 m0 = s_stage[wrp][bi][lane], m1 = s_stage[wrp][bi][lane + 32];
            float w = s_wn2[r - rs], wp = s_wb[r - rs];
            racc0.x += wp * m0.x; racc0.y += wp * m0.y; racc0.z += wp * m0.z; racc0.w += wp * m0.w;
            racc1.x += wp * m1.x; racc1.y += wp * m1.y; racc1.z += wp * m1.z; racc1.w += wp * m1.w;
            float4 n0 = apply4(m0, w, e0, a0), n1 = apply4(m1, w, e1, a1);
            float dr = dot4(n0, kr0) + dot4(n1, kr1);
            float ss = dot4(n0, n0) + dot4(n1, n1);
            float dw = dot4(n0, kw0) + dot4(n1, kw1);
            warpSum3(dr, ss, dw);
            if (lane == 0) { s_dr[r - rs] = dr; s_ss[r - rs] = ss; s_dw[r - rs] = dw; }
            bi ^= 1;
        }
        CPA_WAIT0();
        atomicAdd(&s_acc[4 * lane + 0], racc0.x); atomicAdd(&s_acc[4 * lane + 1], racc0.y);
        atomicAdd(&s_acc[4 * lane + 2], racc0.z); atomicAdd(&s_acc[4 * lane + 3], racc0.w);
        atomicAdd(&s_acc[128 + 4 * lane + 0], racc1.x); atomicAdd(&s_acc[128 + 4 * lane + 1], racc1.y);
        atomicAdd(&s_acc[128 + 4 * lane + 2], racc1.z); atomicAdd(&s_acc[128 + 4 * lane + 3], racc1.w);
        __syncthreads();
        float er = 0.f, ew = 0.f;
        if (t < nb) {
            float nrm = sqrtf(s_ss[t]);
            float beta_r = __ldcg(&g_sc[5 * 8 + 0]), kn_r = __ldcg(&g_sc[5 * 8 + 6]);
            float beta_w = __ldcg(&g_sc[6 * 8 + 0]), kn_w = __ldcg(&g_sc[6 * 8 + 6]);
            float simr = __fdividef(s_dr[t], nrm * kn_r + EPSF); g_simr[rs + t] = simr; er = __expf(beta_r * simr);
            float simw = __fdividef(s_dw[t], nrm * kn_w + EPSF); g_simw[rs + t] = simw; ew = __expf(beta_w * simw);
        }
        float sr = blockSumB(er), sw = blockSumB(ew);
        if (t == 0) { atomicAdd(&g_S[10], sr); atomicAdd(&g_S[12], sw); }
        atomicAdd(&g_reads[1 * Mm + t], s_acc[t]);
    }
    gridbar(9);
    ADDR_PHASE(2, 3);
    PIPE_ISSUE(g_mem, rs + wrp, 0);                 // U3 prefetch
    gridbar(10);

    // ===== U3: read mem2; apply w2 then w3; reads[2] on mem3; sim kr3 on mem4 =====
    {
        if (t < nb) {
            s_wn3[t] = s_wshw[t] / (__ldcg(&g_S[13]) + EPSF);
            s_wb[t]  = s_wshr[t] / (__ldcg(&g_S[11]) + EPSF);
        }
        s_acc[t] = 0.f;
        __syncthreads();
        float4 e20 = __ldcg((const float4*)(g_e + 2 * Mm) + lane), e21 = __ldcg((const float4*)(g_e + 2 * Mm) + lane + 32);
        float4 a20 = __ldcg((const float4*)(g_a + 2 * Mm) + lane), a21 = __ldcg((const float4*)(g_a + 2 * Mm) + lane + 32);
        float4 e30 = __ldcg((const float4*)(g_e + 3 * Mm) + lane), e31 = __ldcg((const float4*)(g_e + 3 * Mm) + lane + 32);
        float4 a30 = __ldcg((const float4*)(g_a + 3 * Mm) + lane), a31 = __ldcg((const float4*)(g_a + 3 * Mm) + lane + 32);
        float4 kr0 = __ldcg((const float4*)(g_kr + 3 * Mm) + lane), kr1 = __ldcg((const float4*)(g_kr + 3 * Mm) + lane + 32);
        float4 racc0 = make_float4(0, 0, 0, 0), racc1 = make_float4(0, 0, 0, 0);
        int bi = 0;
        for (int r = rs + wrp; r < re; r += NWARP) {
            PIPE_ISSUE(g_mem, r + NWARP, bi ^ 1);
            CPA_WAIT1();
            float4 m0 = s_stage[wrp][bi][lane], m1 = s_stage[wrp][bi][lane + 32];
            float w2 = s_wn2[r - rs], w3 = s_wn3[r - rs], wp = s_wb[r - rs];
            m0 = apply4(m0, w2, e20, a20); m1 = apply4(m1, w2, e21, a21);   // mem3
            racc0.x += wp * m0.x; racc0.y += wp * m0.y; racc0.z += wp * m0.z; racc0.w += wp * m0.w;
            racc1.x += wp * m1.x; racc1.y += wp * m1.y; racc1.z += wp * m1.z; racc1.w += wp * m1.w;
            float4 n0 = apply4(m0, w3, e30, a30), n1 = apply4(m1, w3, e31, a31);  // mem4
            float dr = dot4(n0, kr0) + dot4(n1, kr1);
            float ss = dot4(n0, n0) + dot4(n1, n1);
            warpSum2(dr, ss);
            if (lane == 0) { s_dr[r - rs] = dr; s_ss[r - rs] = ss; }
            bi ^= 1;
        }
        CPA_WAIT0();
        atomicAdd(&s_acc[4 * lane + 0], racc0.x); atomicAdd(&s_acc[4 * lane + 1], racc0.y);
        atomicAdd(&s_acc[4 * lane + 2], racc0.z); atomicAdd(&s_acc[4 * lane + 3], racc0.w);
        atomicAdd(&s_acc[128 + 4 * lane + 0], racc1.x); atomicAdd(&s_acc[128 + 4 * lane + 1], racc1.y);
        atomicAdd(&s_acc[128 + 4 * lane + 2], racc1.z); atomicAdd(&s_acc[128 + 4 * lane + 3], racc1.w);
        __syncthreads();
        float er = 0.f;
        if (t < nb) {
            float beta_r = __ldcg(&g_sc[7 * 8 + 0]), kn_r = __ldcg(&g_sc[7 * 8 + 6]);
            float simr = __fdividef(s_dr[t], sqrtf(s_ss[t]) * kn_r + EPSF);
            g_simr[rs + t] = simr; er = __expf(beta_r * simr);
        }
        float sr = blockSumB(er);
        if (t == 0) atomicAdd(&g_S[14], sr);
        atomicAdd(&g_reads[2 * Mm + t], s_acc[t]);
    }
    gridbar(11);
    ADDR_PHASE(3, -1);
    PIPE_ISSUE(g_mem, rs + wrp, 0);                 // FINAL prefetch
    gridbar(12);

    // ===== FINAL: reads[3] on mem4 = apply(w2, w3) over mem2 =====
    {
        if (t < nb) s_wb[t] = s_wshr[t] / (__ldcg(&g_S[15]) + EPSF);
        s_acc[t] = 0.f;
        __syncthreads();
        float4 e20 = __ldcg((const float4*)(g_e + 2 * Mm) + lane), e21 = __ldcg((const float4*)(g_e + 2 * Mm) + lane + 32);
        float4 a20 = __ldcg((const float4*)(g_a + 2 * Mm) + lane), a21 = __ldcg((const float4*)(g_a + 2 * Mm) + lane + 32);
        float4 e30 = __ldcg((const float4*)(g_e + 3 * Mm) + lane), e31 = __ldcg((const float4*)(g_e + 3 * Mm) + lane + 32);
        float4 a30 = __ldcg((const float4*)(g_a + 3 * Mm) + lane), a31 = __ldcg((const float4*)(g_a + 3 * Mm) + lane + 32);
        float4 racc0 = make_float4(0, 0, 0, 0), racc1 = make_float4(0, 0, 0, 0);
        int bi = 0;
        for (int r = rs + wrp; r < re; r += NWARP) {
            PIPE_ISSUE(g_mem, r + NWARP, bi ^ 1);
            CPA_WAIT1();
            float4 m0 = s_stage[wrp][bi][lane], m1 = s_stage[wrp][bi][lane + 32];
            float w2 = s_wn2[r - rs], w3 = s_wn3[r - rs], wr = s_wb[r - rs];
            m0 = apply4(m0, w2, e20, a20); m1 = apply4(m1, w2, e21, a21);
            m0 = apply4(m0, w3, e30, a30); m1 = apply4(m1, w3, e31, a31);
            racc0.x += wr * m0.x; racc0.y += wr * m0.y; racc0.z += wr * m0.z; racc0.w += wr * m0.w;
            racc1.x += wr * m1.x; racc1.y += wr * m1.y; racc1.z += wr * m1.z; racc1.w += wr * m1.w;
            bi ^= 1;
        }
        CPA_WAIT0();
        atomicAdd(&s_acc[4 * lane + 0], racc0.x); atomicAdd(&s_acc[4 * lane + 1], racc0.y);
        atomicAdd(&s_acc[4 * lane + 2], racc0.z); atomicAdd(&s_acc[4 * lane + 3], racc0.w);
        atomicAdd(&s_acc[128 + 4 * lane + 0], racc1.x); atomicAdd(&s_acc[128 + 4 * lane + 1], racc1.y);
        atomicAdd(&s_acc[128 + 4 * lane + 2], racc1.z); atomicAdd(&s_acc[128 + 4 * lane + 3], racc1.w);
        __syncthreads();
        atomicAdd(&g_reads[3 * Mm + t], s_acc[t]);
    }
    gridbar(13);

    // ===== OUT: 4 rows per block across 512 blocks (warps 0-3) =====
    if (b < 512) {
        for (int j = t; j < CTRLD; j += PBLK) s_buf[j] = __ldcg(&g_reads[j]);
        __syncthreads();
        if (wrp < 4) {
            int row = b * 4 + wrp;               // 0..2047
            const float4* w4 = (const float4*)(W_out + (size_t)row * CTRLD);
            const float4* r4 = (const float4*)s_buf;
            float s = 0.f;
#pragma unroll 8
            for (int j = lane; j < 256; j += 32) s += dot4(w4[j], r4[j]);
            s = warpSum(s);
            if (lane == 0) out[row] = s + b_out[row];
        }
    }
}

// ---------------- launch ----------------
extern "C" void kernel_launch(void* const* d_in, const int* in_sizes, int n_in,
                              void* d_out, int out_size) {
    const float* x          = (const float*)d_in[0];
    const float* prev_reads = (const float*)d_in[1];
    const float* prev_h     = (const float*)d_in[2];
    const float* prev_c     = (const float*)d_in[3];
    const float* memory     = (const float*)d_in[4];
    const float* prev_rw    = (const float*)d_in[5];
    const float* prev_ww    = (const float*)d_in[6];
    const float* W_ih       = (const float*)d_in[7];
    const float* W_hh       = (const float*)d_in[8];
    const float* b_lstm     = (const float*)d_in[9];
    const float* W_out      = (const float*)d_in[10];
    const float* b_out      = (const float*)d_in[11];
    const float* Ww         = (const float*)d_in[12];
    const float* bw         = (const float*)d_in[13];
    const float* Wr         = (const float*)d_in[14];
    const float* br         = (const float*)d_in[15];
    float* out = (float*)d_out;

    k_init<<<1, 1024>>>();
    k_all<<<PGRID, PBLK>>>(x, prev_reads, prev_h, prev_c, memory, prev_rw, prev_ww,
                           W_ih, W_hh, b_lstm, W_out, b_out, Ww, bw, Wr, br, out);
}